// round 1
// baseline (speedup 1.0000x reference)
#include <cuda_runtime.h>
#include <math.h>

// Problem dims (fixed)
#define BATCH 32
#define SEQ   512
#define N_TOK (BATCH * SEQ)   // 16384
#define DIM   256
#define HID   512
#define PFF   2048
#define NHD   8
#define HDD   64
#define NMAXN 15

// ---------------- scratch (device globals: allocation-free) ----------------
__device__ float g_x[N_TOK * DIM];
__device__ float g_agg[N_TOK * DIM];
__device__ float g_tmp[N_TOK * DIM];
__device__ float g_h[N_TOK * HID];
__device__ float g_q[N_TOK * HID];
__device__ float g_k[N_TOK * HID];
__device__ float g_v[N_TOK * HID];
__device__ float g_o[N_TOK * HID];
__device__ float g_t1[N_TOK * HID];
__device__ float g_f1[N_TOK * PFF];

// ---------------- block reduce (256 threads) ----------------
__device__ __forceinline__ float blockSum256(float v) {
    __shared__ float sh[8];
    int lane = threadIdx.x & 31, w = threadIdx.x >> 5;
#pragma unroll
    for (int o = 16; o; o >>= 1) v += __shfl_xor_sync(0xffffffffu, v, o);
    __syncthreads();
    if (lane == 0) sh[w] = v;
    __syncthreads();
    float r = sh[0];
#pragma unroll
    for (int i = 1; i < 8; i++) r += sh[i];
    return r;
}

// ---------------- embed + PE + time ----------------
__global__ void embed_kernel(const int* __restrict__ src,
                             const float* __restrict__ tint,
                             const float* __restrict__ emb,
                             const float* __restrict__ timeW,
                             const float* __restrict__ timeb,
                             float* __restrict__ x) {
    int n = blockIdx.x;
    int d = threadIdx.x;        // 256
    int s = n & (SEQ - 1);
    int v = src[n];
    float e = emb[(size_t)v * DIM + d];
    int i2 = (d >> 1) * 2;
    // div = exp(arange(0,D,2) * (-ln(10000)/D))
    float div = expf((float)i2 * (-9.210340371976184f / (float)DIM));
    float ang = (float)s * div;
    float pe = (d & 1) ? cosf(ang) : sinf(ang);
    float tv = tint[n];
    x[n * DIM + d] = e + pe + tv * timeW[d] + timeb[d];
}

// ---------------- neighbor mean aggregation ----------------
__global__ void agg_kernel(const int* __restrict__ nidx,
                           const int* __restrict__ ncnt,
                           const float* __restrict__ x,
                           float* __restrict__ agg) {
    int n = blockIdx.x;
    int d = threadIdx.x;
    int cnt = ncnt[n];
    float sum = 0.f;
    for (int j = 0; j < cnt; j++) {
        int idx = nidx[n * NMAXN + j];
        sum += x[idx * DIM + d];
    }
    int dv = cnt > 1 ? cnt : 1;
    agg[n * DIM + d] = sum / (float)dv;
}

// ---------------- soc LN + relu + select + x update (writes x out too) ----
__global__ void soc_ln_kernel(const float* __restrict__ tmp,
                              const float* __restrict__ g,
                              const float* __restrict__ beta,
                              const int* __restrict__ ncnt,
                              const int* __restrict__ src,
                              float* __restrict__ x,
                              float* __restrict__ out_x) {
    int n = blockIdx.x;
    int d = threadIdx.x;
    float tv = tmp[n * DIM + d];
    float mu = blockSum256(tv) * (1.f / DIM);
    float df = tv - mu;
    float var = blockSum256(df * df) * (1.f / DIM);
    float y = df * rsqrtf(var + 1e-5f) * g[d] + beta[d];
    y = fmaxf(y, 0.f);
    float xv = x[n * DIM + d];
    float soc = (ncnt[n] > 0) ? y : xv;
    if (src[n] == 0) soc = 0.f;    // PAD
    float xo = xv + 0.2f * soc;
    x[n * DIM + d] = xo;
    out_x[n * DIM + d] = xo;
}

// ---------------- LayerNorm over 512 (256 threads x 2) ----------------
__global__ void ln512_kernel(const float* __restrict__ in,
                             const float* __restrict__ g,
                             const float* __restrict__ b,
                             float* __restrict__ out) {
    int n = blockIdx.x;
    int t = threadIdx.x;
    const float* r = in + (size_t)n * HID;
    float a0 = r[t], a1 = r[t + 256];
    float mu = blockSum256(a0 + a1) * (1.f / HID);
    float d0 = a0 - mu, d1 = a1 - mu;
    float var = blockSum256(d0 * d0 + d1 * d1) * (1.f / HID);
    float inv = rsqrtf(var + 1e-5f);
    out[(size_t)n * HID + t] = d0 * inv * g[t] + b[t];
    out[(size_t)n * HID + t + 256] = d1 * inv * g[t + 256] + b[t + 256];
}

// ---------------- SGEMM: C = act(A[MxK] @ Bw[KxN] + bias [+ Cin]) ----------
// 128x128 tile, BK=8, 256 threads, 8x8 microtile. M,N,K multiples of 128/8.
template <bool RELU, bool RES>
__global__ void sgemm_kernel(const float* __restrict__ A,
                             const float* __restrict__ Bw,
                             const float* __restrict__ bias,
                             const float* __restrict__ Cin,
                             float* __restrict__ C,
                             int M, int Nn, int K) {
    __shared__ float As[8][128];
    __shared__ float Bs[8][128];
    int tid = threadIdx.x;
    int row0 = blockIdx.y * 128, col0 = blockIdx.x * 128;
    int tx = tid & 15, ty = tid >> 4;
    int arow = tid >> 1, acol = (tid & 1) * 4;
    int brow = tid >> 5, bcol = (tid & 31) * 4;
    const float* Aptr = A + (size_t)(row0 + arow) * K + acol;
    const float* Bptr = Bw + (size_t)brow * Nn + col0 + bcol;

    float acc[8][8];
#pragma unroll
    for (int i = 0; i < 8; i++)
#pragma unroll
        for (int j = 0; j < 8; j++) acc[i][j] = 0.f;

    for (int k0 = 0; k0 < K; k0 += 8) {
        float4 a4 = *(const float4*)(Aptr + k0);
        float4 b4 = *(const float4*)(Bptr + (size_t)k0 * Nn);
        As[acol + 0][arow] = a4.x;
        As[acol + 1][arow] = a4.y;
        As[acol + 2][arow] = a4.z;
        As[acol + 3][arow] = a4.w;
        *(float4*)&Bs[brow][bcol] = b4;
        __syncthreads();
#pragma unroll
        for (int k = 0; k < 8; k++) {
            float4 A0 = *(const float4*)&As[k][ty * 8];
            float4 A1 = *(const float4*)&As[k][ty * 8 + 4];
            float4 B0 = *(const float4*)&Bs[k][tx * 8];
            float4 B1 = *(const float4*)&Bs[k][tx * 8 + 4];
            float ar[8] = {A0.x, A0.y, A0.z, A0.w, A1.x, A1.y, A1.z, A1.w};
            float br[8] = {B0.x, B0.y, B0.z, B0.w, B1.x, B1.y, B1.z, B1.w};
#pragma unroll
            for (int i = 0; i < 8; i++)
#pragma unroll
                for (int j = 0; j < 8; j++) acc[i][j] += ar[i] * br[j];
        }
        __syncthreads();
    }

    int crow = row0 + ty * 8;
    int ccol = col0 + tx * 8;
    float bs[8];
#pragma unroll
    for (int j = 0; j < 8; j++) bs[j] = bias[ccol + j];
#pragma unroll
    for (int i = 0; i < 8; i++) {
        float o[8];
#pragma unroll
        for (int j = 0; j < 8; j++) o[j] = acc[i][j] + bs[j];
        if (RES) {
            const float* rp = Cin + (size_t)(crow + i) * Nn + ccol;
            float4 r0 = *(const float4*)rp;
            float4 r1 = *(const float4*)(rp + 4);
            o[0] += r0.x; o[1] += r0.y; o[2] += r0.z; o[3] += r0.w;
            o[4] += r1.x; o[5] += r1.y; o[6] += r1.z; o[7] += r1.w;
        }
        if (RELU) {
#pragma unroll
            for (int j = 0; j < 8; j++) o[j] = fmaxf(o[j], 0.f);
        }
        float* cp = C + (size_t)(crow + i) * Nn + ccol;
        *(float4*)cp = make_float4(o[0], o[1], o[2], o[3]);
        *(float4*)(cp + 4) = make_float4(o[4], o[5], o[6], o[7]);
    }
}

// ---------------- flash attention (BQ=64, BK=32, HD=64) ----------------
// grid (SEQ/64, BATCH*NHD), 256 threads. thread = (q=tid>>2, g4=tid&3)
__global__ void attn_kernel(const float* __restrict__ Q,
                            const float* __restrict__ K,
                            const float* __restrict__ V,
                            const int* __restrict__ src,
                            float* __restrict__ O) {
    __shared__ float q_s[64][65];
    __shared__ float k_s[32][65];
    __shared__ float v_s[32][65];
    __shared__ float s_s[64][33];
    __shared__ float kmask[32];

    int bh = blockIdx.y;
    int b = bh >> 3;
    int hh = bh & 7;
    int q0 = blockIdx.x * 64;
    int tid = threadIdx.x;

    const float* Qb = Q + ((size_t)(b * SEQ + q0)) * HID + hh * HDD;
    for (int i = tid; i < 64 * 64; i += 256) {
        int r = i >> 6, d = i & 63;
        q_s[r][d] = Qb[r * HID + d];
    }

    int q = tid >> 2, g4 = tid & 3;
    float m_run = -1e30f, l_run = 0.f;
    float o_acc[16];
#pragma unroll
    for (int j = 0; j < 16; j++) o_acc[j] = 0.f;

    for (int k0 = 0; k0 < SEQ; k0 += 32) {
        __syncthreads();  // protect k_s/v_s/kmask from prior iteration readers
        const float* Kb = K + ((size_t)(b * SEQ + k0)) * HID + hh * HDD;
        const float* Vb = V + ((size_t)(b * SEQ + k0)) * HID + hh * HDD;
        for (int i = tid; i < 32 * 64; i += 256) {
            int r = i >> 6, d = i & 63;
            k_s[r][d] = Kb[r * HID + d];
            v_s[r][d] = Vb[r * HID + d];
        }
        if (tid < 32) kmask[tid] = (src[b * SEQ + k0 + tid] != 0) ? 0.f : -1e10f;
        __syncthreads();

        // scores: 8 keys per thread, q-value hoisted to register per d
        float sc[8];
#pragma unroll
        for (int kk8 = 0; kk8 < 8; kk8++) sc[kk8] = 0.f;
#pragma unroll 16
        for (int d = 0; d < 64; d++) {
            float qd = q_s[q][d];
#pragma unroll
            for (int kk8 = 0; kk8 < 8; kk8++)
                sc[kk8] += qd * k_s[g4 * 8 + kk8][d];
        }
        float tmax = -1e30f;
#pragma unroll
        for (int kk8 = 0; kk8 < 8; kk8++) {
            sc[kk8] = sc[kk8] * 0.125f + kmask[g4 * 8 + kk8];
            tmax = fmaxf(tmax, sc[kk8]);
        }
        tmax = fmaxf(tmax, __shfl_xor_sync(0xffffffffu, tmax, 1));
        tmax = fmaxf(tmax, __shfl_xor_sync(0xffffffffu, tmax, 2));
        float m_new = fmaxf(m_run, tmax);
        float scale = expf(m_run - m_new);
        float lsum = 0.f;
#pragma unroll
        for (int kk8 = 0; kk8 < 8; kk8++) {
            float p = expf(sc[kk8] - m_new);
            s_s[q][g4 * 8 + kk8] = p;
            lsum += p;
        }
        lsum += __shfl_xor_sync(0xffffffffu, lsum, 1);
        lsum += __shfl_xor_sync(0xffffffffu, lsum, 2);
        l_run = l_run * scale + lsum;
        m_run = m_new;
#pragma unroll
        for (int j = 0; j < 16; j++) o_acc[j] *= scale;
        __syncthreads();

        // o accumulation: dims interleaved d = g4 + 4*j (conflict-free)
        for (int kk = 0; kk < 32; kk++) {
            float p = s_s[q][kk];
#pragma unroll
            for (int j = 0; j < 16; j++)
                o_acc[j] += p * v_s[kk][g4 + 4 * j];
        }
    }

    float inv = 1.f / l_run;
    float* Ob = O + ((size_t)(b * SEQ + q0 + q)) * HID + hh * HDD;
#pragma unroll
    for (int j = 0; j < 16; j++) Ob[g4 + 4 * j] = o_acc[j] * inv;
}

// ---------------- final copy of h into output ----------------
__global__ void copy_kernel(const float* __restrict__ in, float* __restrict__ out, int n) {
    int i = blockIdx.x * blockDim.x + threadIdx.x;
    if (i < n) out[i] = in[i];
}

// ---------------- host side ----------------
template <bool RELU, bool RES>
static void launch_gemm(const float* A, const float* Bw, const float* bias,
                        const float* Cin, float* C, int M, int Nn, int K) {
    dim3 grid(Nn / 128, M / 128);
    sgemm_kernel<RELU, RES><<<grid, 256>>>(A, Bw, bias, Cin, C, M, Nn, K);
}

extern "C" void kernel_launch(void* const* d_in, const int* in_sizes, int n_in,
                              void* d_out, int out_size) {
    const int*   src   = (const int*)d_in[0];
    // d_in[1] = src_lengths (unused)
    const int*   nidx  = (const int*)d_in[2];
    const int*   ncnt  = (const int*)d_in[3];
    const float* tint  = (const float*)d_in[4];
    const float* emb   = (const float*)d_in[5];
    const float* timeW = (const float*)d_in[6];
    const float* timeb = (const float*)d_in[7];
    const float* socW  = (const float*)d_in[8];
    const float* socb  = (const float*)d_in[9];
    const float* socg  = (const float*)d_in[10];
    const float* socbe = (const float*)d_in[11];
    const float* projW = (const float*)d_in[12];
    const float* projb = (const float*)d_in[13];
    const float* Wq    = (const float*)d_in[14];
    const float* bq    = (const float*)d_in[15];
    const float* Wk    = (const float*)d_in[16];
    const float* bk    = (const float*)d_in[17];
    const float* Wv    = (const float*)d_in[18];
    const float* bv    = (const float*)d_in[19];
    const float* Wo    = (const float*)d_in[20];
    const float* bo    = (const float*)d_in[21];
    const float* ln1g  = (const float*)d_in[22];
    const float* ln1b  = (const float*)d_in[23];
    const float* W1    = (const float*)d_in[24];
    const float* b1    = (const float*)d_in[25];
    const float* W2    = (const float*)d_in[26];
    const float* b2    = (const float*)d_in[27];
    const float* ln2g  = (const float*)d_in[28];
    const float* ln2b  = (const float*)d_in[29];

    float *x, *agg, *tmp, *h, *q, *k, *v, *o, *t1, *f1;
    void* p;
    cudaGetSymbolAddress(&p, g_x);   x   = (float*)p;
    cudaGetSymbolAddress(&p, g_agg); agg = (float*)p;
    cudaGetSymbolAddress(&p, g_tmp); tmp = (float*)p;
    cudaGetSymbolAddress(&p, g_h);   h   = (float*)p;
    cudaGetSymbolAddress(&p, g_q);   q   = (float*)p;
    cudaGetSymbolAddress(&p, g_k);   k   = (float*)p;
    cudaGetSymbolAddress(&p, g_v);   v   = (float*)p;
    cudaGetSymbolAddress(&p, g_o);   o   = (float*)p;
    cudaGetSymbolAddress(&p, g_t1);  t1  = (float*)p;
    cudaGetSymbolAddress(&p, g_f1);  f1  = (float*)p;

    float* out_h = (float*)d_out;                 // [N_TOK, HID]
    float* out_x = (float*)d_out + N_TOK * HID;   // [N_TOK, DIM]

    // 1. embedding + positional + time
    embed_kernel<<<N_TOK, 256>>>(src, tint, emb, timeW, timeb, x);
    // 2. neighbor aggregation
    agg_kernel<<<N_TOK, 256>>>(nidx, ncnt, x, agg);
    // 3. soc linear: tmp = x + agg @ socW + socb
    launch_gemm<false, true>(agg, socW, socb, x, tmp, N_TOK, DIM, DIM);
    // 4. soc LN + relu + select + x += 0.2*soc (writes out_x)
    soc_ln_kernel<<<N_TOK, 256>>>(tmp, socg, socbe, ncnt, src, x, out_x);
    // 5. projection: h = x @ projW + projb
    launch_gemm<false, false>(x, projW, projb, nullptr, h, N_TOK, HID, DIM);

    for (int l = 0; l < 2; l++) {
        const float* Wql = Wq + (size_t)l * HID * HID;
        const float* Wkl = Wk + (size_t)l * HID * HID;
        const float* Wvl = Wv + (size_t)l * HID * HID;
        const float* Wol = Wo + (size_t)l * HID * HID;
        launch_gemm<false, false>(h, Wql, bq + l * HID, nullptr, q, N_TOK, HID, HID);
        launch_gemm<false, false>(h, Wkl, bk + l * HID, nullptr, k, N_TOK, HID, HID);
        launch_gemm<false, false>(h, Wvl, bv + l * HID, nullptr, v, N_TOK, HID, HID);
        attn_kernel<<<dim3(SEQ / 64, BATCH * NHD), 256>>>(q, k, v, src, o);
        // t1 = h + o @ Wo + bo ; h = LN1(t1)
        launch_gemm<false, true>(o, Wol, bo + l * HID, h, t1, N_TOK, HID, HID);
        ln512_kernel<<<N_TOK, 256>>>(t1, ln1g + l * HID, ln1b + l * HID, h);
        // f1 = relu(h @ W1 + b1) ; t1 = h + f1 @ W2 + b2 ; h = LN2(t1)
        launch_gemm<true, false>(h, W1 + (size_t)l * HID * PFF, b1 + l * PFF,
                                 nullptr, f1, N_TOK, PFF, HID);
        launch_gemm<false, true>(f1, W2 + (size_t)l * PFF * HID, b2 + l * HID,
                                 h, t1, N_TOK, HID, PFF);
        ln512_kernel<<<N_TOK, 256>>>(t1, ln2g + l * HID, ln2b + l * HID, h);
    }

    int nh = N_TOK * HID;
    copy_kernel<<<(nh + 255) / 256, 256>>>(h, out_h, nh);
}

// round 3
// speedup vs baseline: 1.9167x; 1.9167x over previous
#include <cuda_runtime.h>
#include <math.h>
#include <stdint.h>

// Problem dims (fixed)
#define BATCH 32
#define SEQ   512
#define N_TOK (BATCH * SEQ)   // 16384
#define DIM   256
#define HID   512
#define PFF   2048
#define NHD   8
#define HDD   64
#define NMAXN 15

// ---------------- scratch (device globals: allocation-free) ----------------
__device__ float g_x[N_TOK * DIM];
__device__ float g_agg[N_TOK * DIM];
__device__ float g_tmp[N_TOK * DIM];
__device__ float g_h[N_TOK * HID];
__device__ float g_q[N_TOK * HID];
__device__ float g_k[N_TOK * HID];
__device__ float g_v[N_TOK * HID];
__device__ float g_o[N_TOK * HID];
__device__ float g_t1[N_TOK * HID];
__device__ float g_f1[N_TOK * PFF];
// transposed weights: socT(65536) projT(131072) then per layer:
// WqT WkT WvT WoT (262144 each), W1T(1048576), W2T(1048576)
#define WT_SOC   0
#define WT_PROJ  65536
#define WT_LAYER 196608
#define WT_PER_L 3145728
__device__ float g_wt[WT_LAYER + 2 * WT_PER_L];

// ======================= helpers =======================
__device__ __forceinline__ uint32_t smem_u32(const void* p) {
    uint32_t a;
    asm("{ .reg .u64 t; cvta.to.shared.u64 t, %1; cvt.u32.u64 %0, t; }" : "=r"(a) : "l"(p));
    return a;
}
__device__ __forceinline__ uint32_t f2tf(float f) {
    uint32_t u;
    asm("cvt.rna.tf32.f32 %0, %1;" : "=r"(u) : "f"(f));
    return u;
}
__device__ __forceinline__ void cp16(uint32_t dst, const void* src) {
    asm volatile("cp.async.cg.shared.global [%0], [%1], 16;" :: "r"(dst), "l"(src));
}
#define CP_COMMIT() asm volatile("cp.async.commit_group;" ::: "memory")
#define CP_WAIT(n)  asm volatile("cp.async.wait_group %0;" :: "n"(n) : "memory")

__device__ __forceinline__ void mma_tf32(float* c, const uint32_t* a, const uint32_t* b) {
    asm volatile(
        "mma.sync.aligned.m16n8k8.row.col.f32.tf32.tf32.f32 "
        "{%0,%1,%2,%3}, {%4,%5,%6,%7}, {%8,%9}, {%0,%1,%2,%3};\n"
        : "+f"(c[0]), "+f"(c[1]), "+f"(c[2]), "+f"(c[3])
        : "r"(a[0]), "r"(a[1]), "r"(a[2]), "r"(a[3]), "r"(b[0]), "r"(b[1]));
}

// Smem geometry: per stage As[128][36] + Bs[128][36] floats
#define TSTRIDE 36
#define STAGE_F (2 * 128 * TSTRIDE)          // 9216 floats per stage
#define GEMM_SMEM (2 * STAGE_F * 4)          // 73728 bytes

// ============== tf32 tensor-core GEMM: C = act(A[M,K] @ Bt[N,K]^T + bias [+Cin]) ==============
// 128x128 CTA tile, BK=32, 256 threads (8 warps = 2x4), warp tile 64x32,
// m16n8k8 tf32 MMA, cp.async double buffering.
template <bool RELU, bool RES>
__global__ void __launch_bounds__(256) tc_gemm(const float* __restrict__ A,
                                               const float* __restrict__ Bt,
                                               const float* __restrict__ bias,
                                               const float* __restrict__ Cin,
                                               float* __restrict__ C,
                                               int M, int N, int K) {
    extern __shared__ float sm[];
    int tid = threadIdx.x;
    int m0 = blockIdx.y * 128, n0 = blockIdx.x * 128;
    int lane = tid & 31, wid = tid >> 5;
    int wm = wid & 1, wn = wid >> 1;       // warp tile: rows wm*64, cols wn*32
    int g = lane >> 2, tig = lane & 3;
    uint32_t sb = smem_u32(sm);

    float acc[4][4][4];
#pragma unroll
    for (int mt = 0; mt < 4; mt++)
#pragma unroll
        for (int nt = 0; nt < 4; nt++)
#pragma unroll
            for (int r = 0; r < 4; r++) acc[mt][nt][r] = 0.f;

    int nk = K >> 5;
    int lrow = tid >> 3, lc4 = (tid & 7) * 4;   // load coords: 32 rows per pass

    // stage issue: A tile [128 x 32] + B tile [128 x 32], 16B chunks
    auto issue = [&](int s, int i) {
#pragma unroll
        for (int p = 0; p < 4; p++) {
            int row = lrow + p * 32;
            uint32_t da = sb + (uint32_t)((s * STAGE_F + row * TSTRIDE + lc4) * 4);
            uint32_t db = da + (uint32_t)(128 * TSTRIDE * 4);
            cp16(da, A + (size_t)(m0 + row) * K + i * 32 + lc4);
            cp16(db, Bt + (size_t)(n0 + row) * K + i * 32 + lc4);
        }
        CP_COMMIT();
    };

    issue(0, 0);
    for (int i = 0; i < nk; i++) {
        int s = i & 1;
        if (i + 1 < nk) {
            issue(s ^ 1, i + 1);
            CP_WAIT(1);
        } else {
            CP_WAIT(0);
        }
        __syncthreads();
        const float* As = sm + s * STAGE_F;
        const float* Bs = As + 128 * TSTRIDE;
#pragma unroll
        for (int kk = 0; kk < 4; kk++) {
            int k = kk * 8 + tig;
            uint32_t af[4][4], bf[4][2];
#pragma unroll
            for (int mt = 0; mt < 4; mt++) {
                int m = wm * 64 + mt * 16 + g;
                af[mt][0] = f2tf(As[m * TSTRIDE + k]);
                af[mt][1] = f2tf(As[(m + 8) * TSTRIDE + k]);
                af[mt][2] = f2tf(As[m * TSTRIDE + k + 4]);
                af[mt][3] = f2tf(As[(m + 8) * TSTRIDE + k + 4]);
            }
#pragma unroll
            for (int nt = 0; nt < 4; nt++) {
                int n = wn * 32 + nt * 8 + g;
                bf[nt][0] = f2tf(Bs[n * TSTRIDE + k]);
                bf[nt][1] = f2tf(Bs[n * TSTRIDE + k + 4]);
            }
#pragma unroll
            for (int mt = 0; mt < 4; mt++)
#pragma unroll
                for (int nt = 0; nt < 4; nt++)
                    mma_tf32(acc[mt][nt], af[mt], bf[nt]);
        }
        __syncthreads();
    }

    // epilogue
#pragma unroll
    for (int mt = 0; mt < 4; mt++) {
#pragma unroll
        for (int nt = 0; nt < 4; nt++) {
            int row0 = m0 + wm * 64 + mt * 16 + g;
            int col = n0 + wn * 32 + nt * 8 + tig * 2;
            float b0 = __ldg(&bias[col]), b1 = __ldg(&bias[col + 1]);
            float v0 = acc[mt][nt][0] + b0, v1 = acc[mt][nt][1] + b1;
            float v2 = acc[mt][nt][2] + b0, v3 = acc[mt][nt][3] + b1;
            if (RES) {
                const float* r0 = Cin + (size_t)row0 * N + col;
                const float* r1 = Cin + (size_t)(row0 + 8) * N + col;
                float2 q0 = *(const float2*)r0;
                float2 q1 = *(const float2*)r1;
                v0 += q0.x; v1 += q0.y; v2 += q1.x; v3 += q1.y;
            }
            if (RELU) {
                v0 = fmaxf(v0, 0.f); v1 = fmaxf(v1, 0.f);
                v2 = fmaxf(v2, 0.f); v3 = fmaxf(v3, 0.f);
            }
            *(float2*)(C + (size_t)row0 * N + col) = make_float2(v0, v1);
            *(float2*)(C + (size_t)(row0 + 8) * N + col) = make_float2(v2, v3);
        }
    }
}

// ---------------- weight transpose: out[c, r] = in[r, c] ----------------
__global__ void transpose_kernel(const float* __restrict__ in, float* __restrict__ out,
                                 int R, int Cc) {
    __shared__ float t[32][33];
    int c0 = blockIdx.x * 32, r0 = blockIdx.y * 32;
    int x = threadIdx.x, y = threadIdx.y;   // (32, 8)
#pragma unroll
    for (int i = 0; i < 32; i += 8) t[y + i][x] = in[(size_t)(r0 + y + i) * Cc + c0 + x];
    __syncthreads();
#pragma unroll
    for (int i = 0; i < 32; i += 8) out[(size_t)(c0 + y + i) * R + r0 + x] = t[x][y + i];
}

// ---------------- block reduce (256 threads) ----------------
__device__ __forceinline__ float blockSum256(float v) {
    __shared__ float sh[8];
    int lane = threadIdx.x & 31, w = threadIdx.x >> 5;
#pragma unroll
    for (int o = 16; o; o >>= 1) v += __shfl_xor_sync(0xffffffffu, v, o);
    __syncthreads();
    if (lane == 0) sh[w] = v;
    __syncthreads();
    float r = sh[0];
#pragma unroll
    for (int i = 1; i < 8; i++) r += sh[i];
    return r;
}

// ---------------- embed + PE + time ----------------
__global__ void embed_kernel(const int* __restrict__ src,
                             const float* __restrict__ tint,
                             const float* __restrict__ emb,
                             const float* __restrict__ timeW,
                             const float* __restrict__ timeb,
                             float* __restrict__ x) {
    int n = blockIdx.x;
    int d = threadIdx.x;
    int s = n & (SEQ - 1);
    int v = src[n];
    float e = emb[(size_t)v * DIM + d];
    int i2 = (d >> 1) * 2;
    float div = expf((float)i2 * (-9.210340371976184f / (float)DIM));
    float ang = (float)s * div;
    float pe = (d & 1) ? cosf(ang) : sinf(ang);
    float tv = tint[n];
    x[n * DIM + d] = e + pe + tv * timeW[d] + timeb[d];
}

// ---------------- neighbor mean aggregation ----------------
__global__ void agg_kernel(const int* __restrict__ nidx,
                           const int* __restrict__ ncnt,
                           const float* __restrict__ x,
                           float* __restrict__ agg) {
    int n = blockIdx.x;
    int d = threadIdx.x;
    int cnt = ncnt[n];
    float sum = 0.f;
    for (int j = 0; j < cnt; j++) {
        int idx = nidx[n * NMAXN + j];
        sum += x[idx * DIM + d];
    }
    int dv = cnt > 1 ? cnt : 1;
    agg[n * DIM + d] = sum / (float)dv;
}

// ---------------- soc LN + relu + select + x update ----------------
__global__ void soc_ln_kernel(const float* __restrict__ tmp,
                              const float* __restrict__ g,
                              const float* __restrict__ beta,
                              const int* __restrict__ ncnt,
                              const int* __restrict__ src,
                              float* __restrict__ x,
                              float* __restrict__ out_x) {
    int n = blockIdx.x;
    int d = threadIdx.x;
    float tv = tmp[n * DIM + d];
    float mu = blockSum256(tv) * (1.f / DIM);
    float df = tv - mu;
    float var = blockSum256(df * df) * (1.f / DIM);
    float y = df * rsqrtf(var + 1e-5f) * g[d] + beta[d];
    y = fmaxf(y, 0.f);
    float xv = x[n * DIM + d];
    float soc = (ncnt[n] > 0) ? y : xv;
    if (src[n] == 0) soc = 0.f;
    float xo = xv + 0.2f * soc;
    x[n * DIM + d] = xo;
    out_x[n * DIM + d] = xo;
}

// ---------------- LayerNorm over 512 ----------------
__global__ void ln512_kernel(const float* __restrict__ in,
                             const float* __restrict__ g,
                             const float* __restrict__ b,
                             float* __restrict__ out) {
    int n = blockIdx.x;
    int t = threadIdx.x;
    const float* r = in + (size_t)n * HID;
    float a0 = r[t], a1 = r[t + 256];
    float mu = blockSum256(a0 + a1) * (1.f / HID);
    float d0 = a0 - mu, d1 = a1 - mu;
    float var = blockSum256(d0 * d0 + d1 * d1) * (1.f / HID);
    float inv = rsqrtf(var + 1e-5f);
    out[(size_t)n * HID + t] = d0 * inv * g[t] + b[t];
    out[(size_t)n * HID + t + 256] = d1 * inv * g[t + 256] + b[t + 256];
}

// ---------------- flash attention (fp32, BQ=64, BK=32, HD=64) ----------------
__global__ void attn_kernel(const float* __restrict__ Q,
                            const float* __restrict__ K,
                            const float* __restrict__ V,
                            const int* __restrict__ src,
                            float* __restrict__ O) {
    __shared__ float q_s[64][65];
    __shared__ float k_s[32][65];
    __shared__ float v_s[32][65];
    __shared__ float s_s[64][33];
    __shared__ float kmask[32];

    int bh = blockIdx.y;
    int b = bh >> 3;
    int hh = bh & 7;
    int q0 = blockIdx.x * 64;
    int tid = threadIdx.x;

    const float* Qb = Q + ((size_t)(b * SEQ + q0)) * HID + hh * HDD;
    for (int i = tid; i < 64 * 64; i += 256) {
        int r = i >> 6, d = i & 63;
        q_s[r][d] = Qb[r * HID + d];
    }

    int q = tid >> 2, g4 = tid & 3;
    float m_run = -1e30f, l_run = 0.f;
    float o_acc[16];
#pragma unroll
    for (int j = 0; j < 16; j++) o_acc[j] = 0.f;

    for (int k0 = 0; k0 < SEQ; k0 += 32) {
        __syncthreads();
        const float* Kb = K + ((size_t)(b * SEQ + k0)) * HID + hh * HDD;
        const float* Vb = V + ((size_t)(b * SEQ + k0)) * HID + hh * HDD;
        for (int i = tid; i < 32 * 64; i += 256) {
            int r = i >> 6, d = i & 63;
            k_s[r][d] = Kb[r * HID + d];
            v_s[r][d] = Vb[r * HID + d];
        }
        if (tid < 32) kmask[tid] = (src[b * SEQ + k0 + tid] != 0) ? 0.f : -1e10f;
        __syncthreads();

        float sc[8];
#pragma unroll
        for (int kk8 = 0; kk8 < 8; kk8++) sc[kk8] = 0.f;
#pragma unroll 16
        for (int d = 0; d < 64; d++) {
            float qd = q_s[q][d];
#pragma unroll
            for (int kk8 = 0; kk8 < 8; kk8++)
                sc[kk8] += qd * k_s[g4 * 8 + kk8][d];
        }
        float tmax = -1e30f;
#pragma unroll
        for (int kk8 = 0; kk8 < 8; kk8++) {
            sc[kk8] = sc[kk8] * 0.125f + kmask[g4 * 8 + kk8];
            tmax = fmaxf(tmax, sc[kk8]);
        }
        tmax = fmaxf(tmax, __shfl_xor_sync(0xffffffffu, tmax, 1));
        tmax = fmaxf(tmax, __shfl_xor_sync(0xffffffffu, tmax, 2));
        float m_new = fmaxf(m_run, tmax);
        float scale = expf(m_run - m_new);
        float lsum = 0.f;
#pragma unroll
        for (int kk8 = 0; kk8 < 8; kk8++) {
            float p = expf(sc[kk8] - m_new);
            s_s[q][g4 * 8 + kk8] = p;
            lsum += p;
        }
        lsum += __shfl_xor_sync(0xffffffffu, lsum, 1);
        lsum += __shfl_xor_sync(0xffffffffu, lsum, 2);
        l_run = l_run * scale + lsum;
        m_run = m_new;
#pragma unroll
        for (int j = 0; j < 16; j++) o_acc[j] *= scale;
        __syncthreads();

        for (int kk = 0; kk < 32; kk++) {
            float p = s_s[q][kk];
#pragma unroll
            for (int j = 0; j < 16; j++)
                o_acc[j] += p * v_s[kk][g4 + 4 * j];
        }
    }

    float inv = 1.f / l_run;
    float* Ob = O + ((size_t)(b * SEQ + q0 + q)) * HID + hh * HDD;
#pragma unroll
    for (int j = 0; j < 16; j++) Ob[g4 + 4 * j] = o_acc[j] * inv;
}

// ---------------- final copy of h into output ----------------
__global__ void copy_kernel(const float* __restrict__ in, float* __restrict__ out, int n) {
    int i = blockIdx.x * blockDim.x + threadIdx.x;
    if (i < n) out[i] = in[i];
}

// ---------------- host side ----------------
template <bool RELU, bool RES>
static void launch_gemm(const float* A, const float* Bt, const float* bias,
                        const float* Cin, float* C, int M, int Nn, int K) {
    dim3 grid(Nn / 128, M / 128);
    tc_gemm<RELU, RES><<<grid, 256, GEMM_SMEM>>>(A, Bt, bias, Cin, C, M, Nn, K);
}

static void launch_transpose(const float* in, float* out, int R, int Cc) {
    transpose_kernel<<<dim3(Cc / 32, R / 32), dim3(32, 8)>>>(in, out, R, Cc);
}

extern "C" void kernel_launch(void* const* d_in, const int* in_sizes, int n_in,
                              void* d_out, int out_size) {
    const int*   src   = (const int*)d_in[0];
    const int*   nidx  = (const int*)d_in[2];
    const int*   ncnt  = (const int*)d_in[3];
    const float* tint  = (const float*)d_in[4];
    const float* emb   = (const float*)d_in[5];
    const float* timeW = (const float*)d_in[6];
    const float* timeb = (const float*)d_in[7];
    const float* socW  = (const float*)d_in[8];
    const float* socb  = (const float*)d_in[9];
    const float* socg  = (const float*)d_in[10];
    const float* socbe = (const float*)d_in[11];
    const float* projW = (const float*)d_in[12];
    const float* projb = (const float*)d_in[13];
    const float* Wq    = (const float*)d_in[14];
    const float* bq    = (const float*)d_in[15];
    const float* Wk    = (const float*)d_in[16];
    const float* bk    = (const float*)d_in[17];
    const float* Wv    = (const float*)d_in[18];
    const float* bv    = (const float*)d_in[19];
    const float* Wo    = (const float*)d_in[20];
    const float* bo    = (const float*)d_in[21];
    const float* ln1g  = (const float*)d_in[22];
    const float* ln1b  = (const float*)d_in[23];
    const float* W1    = (const float*)d_in[24];
    const float* b1    = (const float*)d_in[25];
    const float* W2    = (const float*)d_in[26];
    const float* b2    = (const float*)d_in[27];
    const float* ln2g  = (const float*)d_in[28];
    const float* ln2b  = (const float*)d_in[29];

    float *x, *agg, *tmp, *h, *q, *k, *v, *o, *t1, *f1, *wt;
    void* p;
    cudaGetSymbolAddress(&p, g_x);   x   = (float*)p;
    cudaGetSymbolAddress(&p, g_agg); agg = (float*)p;
    cudaGetSymbolAddress(&p, g_tmp); tmp = (float*)p;
    cudaGetSymbolAddress(&p, g_h);   h   = (float*)p;
    cudaGetSymbolAddress(&p, g_q);   q   = (float*)p;
    cudaGetSymbolAddress(&p, g_k);   k   = (float*)p;
    cudaGetSymbolAddress(&p, g_v);   v   = (float*)p;
    cudaGetSymbolAddress(&p, g_o);   o   = (float*)p;
    cudaGetSymbolAddress(&p, g_t1);  t1  = (float*)p;
    cudaGetSymbolAddress(&p, g_f1);  f1  = (float*)p;
    cudaGetSymbolAddress(&p, g_wt);  wt  = (float*)p;

    cudaFuncSetAttribute(tc_gemm<false, false>, cudaFuncAttributeMaxDynamicSharedMemorySize, GEMM_SMEM);
    cudaFuncSetAttribute(tc_gemm<false, true>,  cudaFuncAttributeMaxDynamicSharedMemorySize, GEMM_SMEM);
    cudaFuncSetAttribute(tc_gemm<true, false>,  cudaFuncAttributeMaxDynamicSharedMemorySize, GEMM_SMEM);

    float* out_h = (float*)d_out;
    float* out_x = (float*)d_out + N_TOK * HID;

    // --- weight transposes into g_wt (Bt layout: [N, K]) ---
    float* socT  = wt + WT_SOC;
    float* projT = wt + WT_PROJ;
    launch_transpose(socW, socT, DIM, DIM);
    launch_transpose(projW, projT, DIM, HID);
    for (int l = 0; l < 2; l++) {
        float* base = wt + WT_LAYER + (size_t)l * WT_PER_L;
        launch_transpose(Wq + (size_t)l * HID * HID, base + 0 * 262144, HID, HID);
        launch_transpose(Wk + (size_t)l * HID * HID, base + 1 * 262144, HID, HID);
        launch_transpose(Wv + (size_t)l * HID * HID, base + 2 * 262144, HID, HID);
        launch_transpose(Wo + (size_t)l * HID * HID, base + 3 * 262144, HID, HID);
        launch_transpose(W1 + (size_t)l * HID * PFF, base + 1048576, HID, PFF);
        launch_transpose(W2 + (size_t)l * PFF * HID, base + 2097152, PFF, HID);
    }

    // 1. embedding + positional + time
    embed_kernel<<<N_TOK, 256>>>(src, tint, emb, timeW, timeb, x);
    // 2. neighbor aggregation
    agg_kernel<<<N_TOK, 256>>>(nidx, ncnt, x, agg);
    // 3. soc linear: tmp = x + agg @ socW + socb
    launch_gemm<false, true>(agg, socT, socb, x, tmp, N_TOK, DIM, DIM);
    // 4. soc LN + relu + select + x += 0.2*soc
    soc_ln_kernel<<<N_TOK, 256>>>(tmp, socg, socbe, ncnt, src, x, out_x);
    // 5. projection: h = x @ projW + projb
    launch_gemm<false, false>(x, projT, projb, (const float*)0, h, N_TOK, HID, DIM);

    for (int l = 0; l < 2; l++) {
        float* base = wt + WT_LAYER + (size_t)l * WT_PER_L;
        launch_gemm<false, false>(h, base + 0 * 262144, bq + l * HID, (const float*)0, q, N_TOK, HID, HID);
        launch_gemm<false, false>(h, base + 1 * 262144, bk + l * HID, (const float*)0, k, N_TOK, HID, HID);
        launch_gemm<false, false>(h, base + 2 * 262144, bv + l * HID, (const float*)0, v, N_TOK, HID, HID);
        attn_kernel<<<dim3(SEQ / 64, BATCH * NHD), 256>>>(q, k, v, src, o);
        launch_gemm<false, true>(o, base + 3 * 262144, bo + l * HID, h, t1, N_TOK, HID, HID);
        ln512_kernel<<<N_TOK, 256>>>(t1, ln1g + l * HID, ln1b + l * HID, h);
        launch_gemm<true, false>(h, base + 1048576, b1 + l * PFF, (const float*)0, f1, N_TOK, PFF, HID);
        launch_gemm<false, true>(f1, base + 2097152, b2 + l * HID, h, t1, N_TOK, HID, PFF);
        ln512_kernel<<<N_TOK, 256>>>(t1, ln2g + l * HID, ln2b + l * HID, h);
    }

    int nh = N_TOK * HID;
    copy_kernel<<<(nh + 255) / 256, 256>>>(h, out_h, nh);
}

// round 4
// speedup vs baseline: 3.4713x; 1.8111x over previous
#include <cuda_runtime.h>
#include <math.h>
#include <stdint.h>

// Problem dims (fixed)
#define BATCH 32
#define SEQ   512
#define N_TOK (BATCH * SEQ)   // 16384
#define DIM   256
#define HID   512
#define PFF   2048
#define NHD   8
#define HDD   64
#define NMAXN 15
#define QKV_STR 1536

// ---------------- scratch (device globals: allocation-free) ----------------
__device__ float g_x[N_TOK * DIM];
__device__ float g_agg[N_TOK * DIM];
__device__ float g_tmp[N_TOK * DIM];
__device__ float g_h[N_TOK * HID];
__device__ float g_qkv[N_TOK * QKV_STR];
__device__ float g_o[N_TOK * HID];
__device__ float g_t1[N_TOK * HID];
__device__ float g_f1[N_TOK * PFF];
__device__ float g_bqkv[2 * QKV_STR];
// transposed weights per layer: qkvT(1536*512) WoT(512*512) W1T W2T
#define WT_SOC   0
#define WT_PROJ  65536
#define WT_LAYER 196608
#define WT_PER_L 3145728
#define L_QKV 0
#define L_WO  786432
#define L_W1  1048576
#define L_W2  2097152
__device__ float g_wt[WT_LAYER + 2 * WT_PER_L];

// ======================= helpers =======================
__device__ __forceinline__ uint32_t smem_u32(const void* p) {
    uint32_t a;
    asm("{ .reg .u64 t; cvta.to.shared.u64 t, %1; cvt.u32.u64 %0, t; }" : "=r"(a) : "l"(p));
    return a;
}
__device__ __forceinline__ uint32_t f2tf(float f) {
    uint32_t u;
    asm("cvt.rna.tf32.f32 %0, %1;" : "=r"(u) : "f"(f));
    return u;
}
__device__ __forceinline__ void cp16(uint32_t dst, const void* src) {
    asm volatile("cp.async.cg.shared.global [%0], [%1], 16;" :: "r"(dst), "l"(src));
}
#define CP_COMMIT() asm volatile("cp.async.commit_group;" ::: "memory")
#define CP_WAIT(n)  asm volatile("cp.async.wait_group %0;" :: "n"(n) : "memory")

__device__ __forceinline__ void mma_tf32(float* c, const uint32_t* a, const uint32_t* b) {
    asm volatile(
        "mma.sync.aligned.m16n8k8.row.col.f32.tf32.tf32.f32 "
        "{%0,%1,%2,%3}, {%4,%5,%6,%7}, {%8,%9}, {%0,%1,%2,%3};\n"
        : "+f"(c[0]), "+f"(c[1]), "+f"(c[2]), "+f"(c[3])
        : "r"(a[0]), "r"(a[1]), "r"(a[2]), "r"(a[3]), "r"(b[0]), "r"(b[1]));
}

// Smem geometry: per stage As[128][36] + Bs[128][36] floats
#define TSTRIDE 36
#define STAGE_F (2 * 128 * TSTRIDE)
#define GEMM_SMEM (2 * STAGE_F * 4)

// ============== tf32 tensor-core GEMM (as Round 3) ==============
template <bool RELU, bool RES>
__global__ void __launch_bounds__(256) tc_gemm(const float* __restrict__ A,
                                               const float* __restrict__ Bt,
                                               const float* __restrict__ bias,
                                               const float* __restrict__ Cin,
                                               float* __restrict__ C,
                                               int M, int N, int K) {
    extern __shared__ float sm[];
    int tid = threadIdx.x;
    int m0 = blockIdx.y * 128, n0 = blockIdx.x * 128;
    int lane = tid & 31, wid = tid >> 5;
    int wm = wid & 1, wn = wid >> 1;
    int g = lane >> 2, tig = lane & 3;
    uint32_t sb = smem_u32(sm);

    float acc[4][4][4];
#pragma unroll
    for (int mt = 0; mt < 4; mt++)
#pragma unroll
        for (int nt = 0; nt < 4; nt++)
#pragma unroll
            for (int r = 0; r < 4; r++) acc[mt][nt][r] = 0.f;

    int nk = K >> 5;
    int lrow = tid >> 3, lc4 = (tid & 7) * 4;

    auto issue = [&](int s, int i) {
#pragma unroll
        for (int p = 0; p < 4; p++) {
            int row = lrow + p * 32;
            uint32_t da = sb + (uint32_t)((s * STAGE_F + row * TSTRIDE + lc4) * 4);
            uint32_t db = da + (uint32_t)(128 * TSTRIDE * 4);
            cp16(da, A + (size_t)(m0 + row) * K + i * 32 + lc4);
            cp16(db, Bt + (size_t)(n0 + row) * K + i * 32 + lc4);
        }
        CP_COMMIT();
    };

    issue(0, 0);
    for (int i = 0; i < nk; i++) {
        int s = i & 1;
        if (i + 1 < nk) {
            issue(s ^ 1, i + 1);
            CP_WAIT(1);
        } else {
            CP_WAIT(0);
        }
        __syncthreads();
        const float* As = sm + s * STAGE_F;
        const float* Bs = As + 128 * TSTRIDE;
#pragma unroll
        for (int kk = 0; kk < 4; kk++) {
            int k = kk * 8 + tig;
            uint32_t af[4][4], bf[4][2];
#pragma unroll
            for (int mt = 0; mt < 4; mt++) {
                int m = wm * 64 + mt * 16 + g;
                af[mt][0] = f2tf(As[m * TSTRIDE + k]);
                af[mt][1] = f2tf(As[(m + 8) * TSTRIDE + k]);
                af[mt][2] = f2tf(As[m * TSTRIDE + k + 4]);
                af[mt][3] = f2tf(As[(m + 8) * TSTRIDE + k + 4]);
            }
#pragma unroll
            for (int nt = 0; nt < 4; nt++) {
                int n = wn * 32 + nt * 8 + g;
                bf[nt][0] = f2tf(Bs[n * TSTRIDE + k]);
                bf[nt][1] = f2tf(Bs[n * TSTRIDE + k + 4]);
            }
#pragma unroll
            for (int mt = 0; mt < 4; mt++)
#pragma unroll
                for (int nt = 0; nt < 4; nt++)
                    mma_tf32(acc[mt][nt], af[mt], bf[nt]);
        }
        __syncthreads();
    }

#pragma unroll
    for (int mt = 0; mt < 4; mt++) {
#pragma unroll
        for (int nt = 0; nt < 4; nt++) {
            int row0 = m0 + wm * 64 + mt * 16 + g;
            int col = n0 + wn * 32 + nt * 8 + tig * 2;
            float b0 = __ldg(&bias[col]), b1 = __ldg(&bias[col + 1]);
            float v0 = acc[mt][nt][0] + b0, v1 = acc[mt][nt][1] + b1;
            float v2 = acc[mt][nt][2] + b0, v3 = acc[mt][nt][3] + b1;
            if (RES) {
                float2 q0 = *(const float2*)(Cin + (size_t)row0 * N + col);
                float2 q1 = *(const float2*)(Cin + (size_t)(row0 + 8) * N + col);
                v0 += q0.x; v1 += q0.y; v2 += q1.x; v3 += q1.y;
            }
            if (RELU) {
                v0 = fmaxf(v0, 0.f); v1 = fmaxf(v1, 0.f);
                v2 = fmaxf(v2, 0.f); v3 = fmaxf(v3, 0.f);
            }
            *(float2*)(C + (size_t)row0 * N + col) = make_float2(v0, v1);
            *(float2*)(C + (size_t)(row0 + 8) * N + col) = make_float2(v2, v3);
        }
    }
}

// ============== tensor-core flash attention ==============
// grid (SEQ/64, BATCH*NHD), 128 threads (4 warps x 16 q-rows).
// qkv packed [N_TOK, 1536]: Q at +0, K at +512, V at +1024 (+ h*64).
// smem floats: Q[64][68] K[64][68] V[64][72] P[64][68] kmask[64]
#define AQS 68
#define AVS 72
#define AOQ 0
#define AOK 4352
#define AOV 8704
#define AOP 13312
#define AOM 17664
#define ATTN_SMEM ((17664 + 64) * 4)

__global__ void __launch_bounds__(128) attn_mma(const float* __restrict__ qkv,
                                                const int* __restrict__ src,
                                                float* __restrict__ O) {
    extern __shared__ float sa[];
    uint32_t* smu = (uint32_t*)sa;
    int bh = blockIdx.y;
    int b = bh >> 3, h = bh & 7;
    int q0 = blockIdx.x * 64;
    int tid = threadIdx.x;
    int lane = tid & 31, w = tid >> 5;
    int g = lane >> 2, tig = lane & 3;

    // load Q (scaled by 1/8, tf32)
    const float* Qg = qkv + (size_t)(b * SEQ + q0) * QKV_STR + h * HDD;
    for (int i = tid; i < 1024; i += 128) {
        int row = i >> 4, c4 = (i & 15) << 2;
        float4 qv = *(const float4*)(Qg + (size_t)row * QKV_STR + c4);
        uint32_t* dst = smu + AOQ + row * AQS + c4;
        dst[0] = f2tf(qv.x * 0.125f); dst[1] = f2tf(qv.y * 0.125f);
        dst[2] = f2tf(qv.z * 0.125f); dst[3] = f2tf(qv.w * 0.125f);
    }

    float o_acc[8][4];
#pragma unroll
    for (int nt = 0; nt < 8; nt++)
#pragma unroll
        for (int r = 0; r < 4; r++) o_acc[nt][r] = 0.f;
    float mr0 = -1e30f, mr1 = -1e30f, lr0 = 0.f, lr1 = 0.f;

    for (int kt = 0; kt < SEQ / 64; kt++) {
        __syncthreads();   // K/V/kmask reuse barrier (also orders Q load on kt==0)
        const float* Kg = qkv + (size_t)(b * SEQ + kt * 64) * QKV_STR + HID + h * HDD;
        const float* Vg = Kg + HID;   // +1024 total
        for (int i = tid; i < 1024; i += 128) {
            int row = i >> 4, c4 = (i & 15) << 2;
            float4 kv = *(const float4*)(Kg + (size_t)row * QKV_STR + c4);
            float4 vv = *(const float4*)(Vg + (size_t)row * QKV_STR + c4);
            uint32_t* dk = smu + AOK + row * AQS + c4;
            dk[0] = f2tf(kv.x); dk[1] = f2tf(kv.y); dk[2] = f2tf(kv.z); dk[3] = f2tf(kv.w);
            uint32_t* dv = smu + AOV + row * AVS + c4;
            dv[0] = f2tf(vv.x); dv[1] = f2tf(vv.y); dv[2] = f2tf(vv.z); dv[3] = f2tf(vv.w);
        }
        if (tid < 64) sa[AOM + tid] = (src[b * SEQ + kt * 64 + tid] != 0) ? 0.f : -1e10f;
        __syncthreads();

        // stage 1: S = Q @ K^T  (per warp: rows w*16..w*16+15, all 64 cols)
        float sc[8][4];
#pragma unroll
        for (int nt = 0; nt < 8; nt++)
#pragma unroll
            for (int r = 0; r < 4; r++) sc[nt][r] = 0.f;
#pragma unroll
        for (int kk = 0; kk < 8; kk++) {
            uint32_t a[4];
            int r0 = (w * 16 + g) * AQS + kk * 8 + tig;
            int r1 = (w * 16 + 8 + g) * AQS + kk * 8 + tig;
            a[0] = smu[AOQ + r0]; a[1] = smu[AOQ + r1];
            a[2] = smu[AOQ + r0 + 4]; a[3] = smu[AOQ + r1 + 4];
#pragma unroll
            for (int nt = 0; nt < 8; nt++) {
                uint32_t bb[2];
                int rb = (nt * 8 + g) * AQS + kk * 8 + tig;
                bb[0] = smu[AOK + rb]; bb[1] = smu[AOK + rb + 4];
                mma_tf32(sc[nt], a, bb);
            }
        }

        // online softmax
        float m0 = -1e30f, m1 = -1e30f;
#pragma unroll
        for (int nt = 0; nt < 8; nt++) {
            float k0 = sa[AOM + nt * 8 + tig * 2];
            float k1 = sa[AOM + nt * 8 + tig * 2 + 1];
            sc[nt][0] += k0; sc[nt][1] += k1;
            sc[nt][2] += k0; sc[nt][3] += k1;
            m0 = fmaxf(m0, fmaxf(sc[nt][0], sc[nt][1]));
            m1 = fmaxf(m1, fmaxf(sc[nt][2], sc[nt][3]));
        }
        m0 = fmaxf(m0, __shfl_xor_sync(0xffffffffu, m0, 1));
        m0 = fmaxf(m0, __shfl_xor_sync(0xffffffffu, m0, 2));
        m1 = fmaxf(m1, __shfl_xor_sync(0xffffffffu, m1, 1));
        m1 = fmaxf(m1, __shfl_xor_sync(0xffffffffu, m1, 2));
        float mn0 = fmaxf(mr0, m0), mn1 = fmaxf(mr1, m1);
        float s0 = __expf(mr0 - mn0), s1 = __expf(mr1 - mn1);
        mr0 = mn0; mr1 = mn1;
        float l0 = 0.f, l1 = 0.f;
        int pr0 = AOP + (w * 16 + g) * AQS + tig * 2;
        int pr1 = AOP + (w * 16 + 8 + g) * AQS + tig * 2;
#pragma unroll
        for (int nt = 0; nt < 8; nt++) {
            float p0 = __expf(sc[nt][0] - mn0);
            float p1 = __expf(sc[nt][1] - mn0);
            float p2 = __expf(sc[nt][2] - mn1);
            float p3 = __expf(sc[nt][3] - mn1);
            l0 += p0 + p1; l1 += p2 + p3;
            smu[pr0 + nt * 8] = f2tf(p0); smu[pr0 + nt * 8 + 1] = f2tf(p1);
            smu[pr1 + nt * 8] = f2tf(p2); smu[pr1 + nt * 8 + 1] = f2tf(p3);
        }
        l0 += __shfl_xor_sync(0xffffffffu, l0, 1);
        l0 += __shfl_xor_sync(0xffffffffu, l0, 2);
        l1 += __shfl_xor_sync(0xffffffffu, l1, 1);
        l1 += __shfl_xor_sync(0xffffffffu, l1, 2);
        lr0 = lr0 * s0 + l0;
        lr1 = lr1 * s1 + l1;
#pragma unroll
        for (int nt = 0; nt < 8; nt++) {
            o_acc[nt][0] *= s0; o_acc[nt][1] *= s0;
            o_acc[nt][2] *= s1; o_acc[nt][3] *= s1;
        }
        __syncwarp();   // P written/read by this warp only

        // stage 2: O += P @ V
#pragma unroll
        for (int kk = 0; kk < 8; kk++) {
            uint32_t a[4];
            int r0 = (w * 16 + g) * AQS + kk * 8 + tig;
            int r1 = (w * 16 + 8 + g) * AQS + kk * 8 + tig;
            a[0] = smu[AOP + r0]; a[1] = smu[AOP + r1];
            a[2] = smu[AOP + r0 + 4]; a[3] = smu[AOP + r1 + 4];
#pragma unroll
            for (int nt = 0; nt < 8; nt++) {
                uint32_t bb[2];
                bb[0] = smu[AOV + (kk * 8 + tig) * AVS + nt * 8 + g];
                bb[1] = smu[AOV + (kk * 8 + tig + 4) * AVS + nt * 8 + g];
                mma_tf32(o_acc[nt], a, bb);
            }
        }
    }

    float i0 = 1.f / lr0, i1 = 1.f / lr1;
    int row0 = b * SEQ + q0 + w * 16 + g;
    float* Ob = O + (size_t)row0 * HID + h * HDD;
#pragma unroll
    for (int nt = 0; nt < 8; nt++) {
        *(float2*)(Ob + nt * 8 + tig * 2) =
            make_float2(o_acc[nt][0] * i0, o_acc[nt][1] * i0);
        *(float2*)(Ob + 8 * HID + nt * 8 + tig * 2) =
            make_float2(o_acc[nt][2] * i1, o_acc[nt][3] * i1);
    }
}

// ---------------- weight transpose ----------------
__global__ void transpose_kernel(const float* __restrict__ in, float* __restrict__ out,
                                 int R, int Cc) {
    __shared__ float t[32][33];
    int c0 = blockIdx.x * 32, r0 = blockIdx.y * 32;
    int x = threadIdx.x, y = threadIdx.y;
#pragma unroll
    for (int i = 0; i < 32; i += 8) t[y + i][x] = in[(size_t)(r0 + y + i) * Cc + c0 + x];
    __syncthreads();
#pragma unroll
    for (int i = 0; i < 32; i += 8) out[(size_t)(c0 + y + i) * R + r0 + x] = t[x][y + i];
}

// ---------------- bias concat (1536) ----------------
__global__ void concat_bias(const float* __restrict__ bq, const float* __restrict__ bk,
                            const float* __restrict__ bv, float* __restrict__ out) {
    int i = blockIdx.x * 256 + threadIdx.x;
    if (i < HID) out[i] = bq[i];
    else if (i < 2 * HID) out[i] = bk[i - HID];
    else out[i] = bv[i - 2 * HID];
}

// ---------------- block reduce (256 threads) ----------------
__device__ __forceinline__ float blockSum256(float v) {
    __shared__ float sh[8];
    int lane = threadIdx.x & 31, w = threadIdx.x >> 5;
#pragma unroll
    for (int o = 16; o; o >>= 1) v += __shfl_xor_sync(0xffffffffu, v, o);
    __syncthreads();
    if (lane == 0) sh[w] = v;
    __syncthreads();
    float r = sh[0];
#pragma unroll
    for (int i = 1; i < 8; i++) r += sh[i];
    return r;
}

// ---------------- embed + PE + time ----------------
__global__ void embed_kernel(const int* __restrict__ src,
                             const float* __restrict__ tint,
                             const float* __restrict__ emb,
                             const float* __restrict__ timeW,
                             const float* __restrict__ timeb,
                             float* __restrict__ x) {
    int n = blockIdx.x;
    int d = threadIdx.x;
    int s = n & (SEQ - 1);
    int v = src[n];
    float e = emb[(size_t)v * DIM + d];
    int i2 = (d >> 1) * 2;
    float div = expf((float)i2 * (-9.210340371976184f / (float)DIM));
    float ang = (float)s * div;
    float pe = (d & 1) ? cosf(ang) : sinf(ang);
    float tv = tint[n];
    x[n * DIM + d] = e + pe + tv * timeW[d] + timeb[d];
}

// ---------------- neighbor mean aggregation ----------------
__global__ void agg_kernel(const int* __restrict__ nidx,
                           const int* __restrict__ ncnt,
                           const float* __restrict__ x,
                           float* __restrict__ agg) {
    int n = blockIdx.x;
    int d = threadIdx.x;
    int cnt = ncnt[n];
    float sum = 0.f;
    for (int j = 0; j < cnt; j++) {
        int idx = nidx[n * NMAXN + j];
        sum += x[idx * DIM + d];
    }
    int dv = cnt > 1 ? cnt : 1;
    agg[n * DIM + d] = sum / (float)dv;
}

// ---------------- soc LN + relu + select + x update ----------------
__global__ void soc_ln_kernel(const float* __restrict__ tmp,
                              const float* __restrict__ g,
                              const float* __restrict__ beta,
                              const int* __restrict__ ncnt,
                              const int* __restrict__ src,
                              float* __restrict__ x,
                              float* __restrict__ out_x) {
    int n = blockIdx.x;
    int d = threadIdx.x;
    float tv = tmp[n * DIM + d];
    float mu = blockSum256(tv) * (1.f / DIM);
    float df = tv - mu;
    float var = blockSum256(df * df) * (1.f / DIM);
    float y = df * rsqrtf(var + 1e-5f) * g[d] + beta[d];
    y = fmaxf(y, 0.f);
    float xv = x[n * DIM + d];
    float soc = (ncnt[n] > 0) ? y : xv;
    if (src[n] == 0) soc = 0.f;
    float xo = xv + 0.2f * soc;
    x[n * DIM + d] = xo;
    out_x[n * DIM + d] = xo;
}

// ---------------- LayerNorm over 512 ----------------
__global__ void ln512_kernel(const float* __restrict__ in,
                             const float* __restrict__ g,
                             const float* __restrict__ b,
                             float* __restrict__ out) {
    int n = blockIdx.x;
    int t = threadIdx.x;
    const float* r = in + (size_t)n * HID;
    float a0 = r[t], a1 = r[t + 256];
    float mu = blockSum256(a0 + a1) * (1.f / HID);
    float d0 = a0 - mu, d1 = a1 - mu;
    float var = blockSum256(d0 * d0 + d1 * d1) * (1.f / HID);
    float inv = rsqrtf(var + 1e-5f);
    out[(size_t)n * HID + t] = d0 * inv * g[t] + b[t];
    out[(size_t)n * HID + t + 256] = d1 * inv * g[t + 256] + b[t + 256];
}

// ---------------- host side ----------------
template <bool RELU, bool RES>
static void launch_gemm(const float* A, const float* Bt, const float* bias,
                        const float* Cin, float* C, int M, int Nn, int K) {
    dim3 grid(Nn / 128, M / 128);
    tc_gemm<RELU, RES><<<grid, 256, GEMM_SMEM>>>(A, Bt, bias, Cin, C, M, Nn, K);
}

static void launch_transpose(const float* in, float* out, int R, int Cc) {
    transpose_kernel<<<dim3(Cc / 32, R / 32), dim3(32, 8)>>>(in, out, R, Cc);
}

extern "C" void kernel_launch(void* const* d_in, const int* in_sizes, int n_in,
                              void* d_out, int out_size) {
    const int*   src   = (const int*)d_in[0];
    const int*   nidx  = (const int*)d_in[2];
    const int*   ncnt  = (const int*)d_in[3];
    const float* tint  = (const float*)d_in[4];
    const float* emb   = (const float*)d_in[5];
    const float* timeW = (const float*)d_in[6];
    const float* timeb = (const float*)d_in[7];
    const float* socW  = (const float*)d_in[8];
    const float* socb  = (const float*)d_in[9];
    const float* socg  = (const float*)d_in[10];
    const float* socbe = (const float*)d_in[11];
    const float* projW = (const float*)d_in[12];
    const float* projb = (const float*)d_in[13];
    const float* Wq    = (const float*)d_in[14];
    const float* bq    = (const float*)d_in[15];
    const float* Wk    = (const float*)d_in[16];
    const float* bk    = (const float*)d_in[17];
    const float* Wv    = (const float*)d_in[18];
    const float* bv    = (const float*)d_in[19];
    const float* Wo    = (const float*)d_in[20];
    const float* bo    = (const float*)d_in[21];
    const float* ln1g  = (const float*)d_in[22];
    const float* ln1b  = (const float*)d_in[23];
    const float* W1    = (const float*)d_in[24];
    const float* b1    = (const float*)d_in[25];
    const float* W2    = (const float*)d_in[26];
    const float* b2    = (const float*)d_in[27];
    const float* ln2g  = (const float*)d_in[28];
    const float* ln2b  = (const float*)d_in[29];

    float *x, *agg, *tmp, *h, *qkv, *o, *t1, *f1, *wt, *bqkv;
    void* p;
    cudaGetSymbolAddress(&p, g_x);    x    = (float*)p;
    cudaGetSymbolAddress(&p, g_agg);  agg  = (float*)p;
    cudaGetSymbolAddress(&p, g_tmp);  tmp  = (float*)p;
    cudaGetSymbolAddress(&p, g_h);    h    = (float*)p;
    cudaGetSymbolAddress(&p, g_qkv);  qkv  = (float*)p;
    cudaGetSymbolAddress(&p, g_o);    o    = (float*)p;
    cudaGetSymbolAddress(&p, g_t1);   t1   = (float*)p;
    cudaGetSymbolAddress(&p, g_f1);   f1   = (float*)p;
    cudaGetSymbolAddress(&p, g_wt);   wt   = (float*)p;
    cudaGetSymbolAddress(&p, g_bqkv); bqkv = (float*)p;

    cudaFuncSetAttribute(tc_gemm<false, false>, cudaFuncAttributeMaxDynamicSharedMemorySize, GEMM_SMEM);
    cudaFuncSetAttribute(tc_gemm<false, true>,  cudaFuncAttributeMaxDynamicSharedMemorySize, GEMM_SMEM);
    cudaFuncSetAttribute(tc_gemm<true, false>,  cudaFuncAttributeMaxDynamicSharedMemorySize, GEMM_SMEM);
    cudaFuncSetAttribute(attn_mma, cudaFuncAttributeMaxDynamicSharedMemorySize, ATTN_SMEM);

    float* out_h = (float*)d_out;
    float* out_x = (float*)d_out + N_TOK * HID;

    // --- weight transposes + bias concat ---
    float* socT  = wt + WT_SOC;
    float* projT = wt + WT_PROJ;
    launch_transpose(socW, socT, DIM, DIM);
    launch_transpose(projW, projT, DIM, HID);
    for (int l = 0; l < 2; l++) {
        float* base = wt + WT_LAYER + (size_t)l * WT_PER_L;
        launch_transpose(Wq + (size_t)l * HID * HID, base + L_QKV + 0 * 262144, HID, HID);
        launch_transpose(Wk + (size_t)l * HID * HID, base + L_QKV + 1 * 262144, HID, HID);
        launch_transpose(Wv + (size_t)l * HID * HID, base + L_QKV + 2 * 262144, HID, HID);
        launch_transpose(Wo + (size_t)l * HID * HID, base + L_WO, HID, HID);
        launch_transpose(W1 + (size_t)l * HID * PFF, base + L_W1, HID, PFF);
        launch_transpose(W2 + (size_t)l * PFF * HID, base + L_W2, PFF, HID);
        concat_bias<<<6, 256>>>(bq + l * HID, bk + l * HID, bv + l * HID, bqkv + l * QKV_STR);
    }

    // front end
    embed_kernel<<<N_TOK, 256>>>(src, tint, emb, timeW, timeb, x);
    agg_kernel<<<N_TOK, 256>>>(nidx, ncnt, x, agg);
    launch_gemm<false, true>(agg, socT, socb, x, tmp, N_TOK, DIM, DIM);
    soc_ln_kernel<<<N_TOK, 256>>>(tmp, socg, socbe, ncnt, src, x, out_x);
    launch_gemm<false, false>(x, projT, projb, (const float*)0, h, N_TOK, HID, DIM);

    for (int l = 0; l < 2; l++) {
        float* base = wt + WT_LAYER + (size_t)l * WT_PER_L;
        // fused QKV
        launch_gemm<false, false>(h, base + L_QKV, bqkv + l * QKV_STR, (const float*)0,
                                  qkv, N_TOK, QKV_STR, HID);
        attn_mma<<<dim3(SEQ / 64, BATCH * NHD), 128, ATTN_SMEM>>>(qkv, src, o);
        launch_gemm<false, true>(o, base + L_WO, bo + l * HID, h, t1, N_TOK, HID, HID);
        ln512_kernel<<<N_TOK, 256>>>(t1, ln1g + l * HID, ln1b + l * HID, h);
        launch_gemm<true, false>(h, base + L_W1, b1 + l * PFF, (const float*)0, f1, N_TOK, PFF, HID);
        launch_gemm<false, true>(f1, base + L_W2, b2 + l * HID, h, t1, N_TOK, HID, PFF);
        // last LN of last layer writes straight to the output buffer
        ln512_kernel<<<N_TOK, 256>>>(t1, ln2g + l * HID, ln2b + l * HID,
                                     (l == 1) ? out_h : h);
    }
}

// round 5
// speedup vs baseline: 3.8845x; 1.1190x over previous
#include <cuda_runtime.h>
#include <math.h>
#include <stdint.h>

// Problem dims (fixed)
#define BATCH 32
#define SEQ   512
#define N_TOK (BATCH * SEQ)   // 16384
#define DIM   256
#define HID   512
#define PFF   2048
#define NHD   8
#define HDD   64
#define NMAXN 15
#define QKV_STR 1536

// ---------------- scratch (device globals: allocation-free) ----------------
__device__ float g_x[N_TOK * DIM];
__device__ float g_agg[N_TOK * DIM];
__device__ float g_tmp[N_TOK * DIM];
__device__ float g_h[N_TOK * HID];
__device__ float g_qkv[N_TOK * QKV_STR];
__device__ float g_o[N_TOK * HID];
__device__ float g_t1[N_TOK * HID];
__device__ float g_f1[N_TOK * PFF];
__device__ float g_bqkv[2 * QKV_STR];
#define WT_SOC   0
#define WT_PROJ  65536
#define WT_LAYER 196608
#define WT_PER_L 3145728
#define L_QKV 0
#define L_WO  786432
#define L_W1  1048576
#define L_W2  2097152
__device__ float g_wt[WT_LAYER + 2 * WT_PER_L];

// ======================= helpers =======================
__device__ __forceinline__ uint32_t smem_u32(const void* p) {
    uint32_t a;
    asm("{ .reg .u64 t; cvta.to.shared.u64 t, %1; cvt.u32.u64 %0, t; }" : "=r"(a) : "l"(p));
    return a;
}
__device__ __forceinline__ uint32_t f2tf(float f) {
    uint32_t u;
    asm("cvt.rna.tf32.f32 %0, %1;" : "=r"(u) : "f"(f));
    return u;
}
__device__ __forceinline__ float roundtf(float f) { return __uint_as_float(f2tf(f)); }
__device__ __forceinline__ void cp16(uint32_t dst, const void* src) {
    asm volatile("cp.async.cg.shared.global [%0], [%1], 16;" :: "r"(dst), "l"(src));
}
#define CP_COMMIT() asm volatile("cp.async.commit_group;" ::: "memory")
#define CP_WAIT(n)  asm volatile("cp.async.wait_group %0;" :: "n"(n) : "memory")

__device__ __forceinline__ void mma_tf32(float* c, const uint32_t* a, const uint32_t* b) {
    asm volatile(
        "mma.sync.aligned.m16n8k8.row.col.f32.tf32.tf32.f32 "
        "{%0,%1,%2,%3}, {%4,%5,%6,%7}, {%8,%9}, {%0,%1,%2,%3};\n"
        : "+f"(c[0]), "+f"(c[1]), "+f"(c[2]), "+f"(c[3])
        : "r"(a[0]), "r"(a[1]), "r"(a[2]), "r"(a[3]), "r"(b[0]), "r"(b[1]));
}

// Smem geometry: per stage As[128][36] + Bs[128][36] floats
#define TSTRIDE 36
#define STAGE_F (2 * 128 * TSTRIDE)
#define GEMM_SMEM (2 * STAGE_F * 4)

// ============== tf32 tensor-core GEMM ==============
// All A and B operands are PRE-ROUNDED to tf32 in gmem -> raw smem loads.
// OP: 0 = plain store, 1 = store tf32-rounded, 2 = tf32-rounded + scale cols<HID by 0.125
template <bool RELU, bool RES, int OP>
__global__ void __launch_bounds__(256) tc_gemm(const float* __restrict__ A,
                                               const float* __restrict__ Bt,
                                               const float* __restrict__ bias,
                                               const float* __restrict__ Cin,
                                               float* __restrict__ C,
                                               int M, int N, int K) {
    extern __shared__ float sm[];
    int tid = threadIdx.x;
    int m0 = blockIdx.y * 128, n0 = blockIdx.x * 128;
    int lane = tid & 31, wid = tid >> 5;
    int wm = wid & 1, wn = wid >> 1;
    int g = lane >> 2, tig = lane & 3;
    uint32_t sb = smem_u32(sm);

    float acc[4][4][4];
#pragma unroll
    for (int mt = 0; mt < 4; mt++)
#pragma unroll
        for (int nt = 0; nt < 4; nt++)
#pragma unroll
            for (int r = 0; r < 4; r++) acc[mt][nt][r] = 0.f;

    int nk = K >> 5;
    int lrow = tid >> 3, lc4 = (tid & 7) * 4;

    auto issue = [&](int s, int i) {
#pragma unroll
        for (int p = 0; p < 4; p++) {
            int row = lrow + p * 32;
            uint32_t da = sb + (uint32_t)((s * STAGE_F + row * TSTRIDE + lc4) * 4);
            uint32_t db = da + (uint32_t)(128 * TSTRIDE * 4);
            cp16(da, A + (size_t)(m0 + row) * K + i * 32 + lc4);
            cp16(db, Bt + (size_t)(n0 + row) * K + i * 32 + lc4);
        }
        CP_COMMIT();
    };

    issue(0, 0);
    for (int i = 0; i < nk; i++) {
        int s = i & 1;
        if (i + 1 < nk) {
            issue(s ^ 1, i + 1);
            CP_WAIT(1);
        } else {
            CP_WAIT(0);
        }
        __syncthreads();
        const uint32_t* As = (const uint32_t*)(sm + s * STAGE_F);
        const uint32_t* Bs = As + 128 * TSTRIDE;
#pragma unroll
        for (int kk = 0; kk < 4; kk++) {
            int k = kk * 8 + tig;
            uint32_t af[4][4], bf[4][2];
#pragma unroll
            for (int mt = 0; mt < 4; mt++) {
                int m = wm * 64 + mt * 16 + g;
                af[mt][0] = As[m * TSTRIDE + k];
                af[mt][1] = As[(m + 8) * TSTRIDE + k];
                af[mt][2] = As[m * TSTRIDE + k + 4];
                af[mt][3] = As[(m + 8) * TSTRIDE + k + 4];
            }
#pragma unroll
            for (int nt = 0; nt < 4; nt++) {
                int n = wn * 32 + nt * 8 + g;
                bf[nt][0] = Bs[n * TSTRIDE + k];
                bf[nt][1] = Bs[n * TSTRIDE + k + 4];
            }
#pragma unroll
            for (int mt = 0; mt < 4; mt++)
#pragma unroll
                for (int nt = 0; nt < 4; nt++)
                    mma_tf32(acc[mt][nt], af[mt], bf[nt]);
        }
        __syncthreads();
    }

#pragma unroll
    for (int mt = 0; mt < 4; mt++) {
#pragma unroll
        for (int nt = 0; nt < 4; nt++) {
            int row0 = m0 + wm * 64 + mt * 16 + g;
            int col = n0 + wn * 32 + nt * 8 + tig * 2;
            float b0 = __ldg(&bias[col]), b1 = __ldg(&bias[col + 1]);
            float v0 = acc[mt][nt][0] + b0, v1 = acc[mt][nt][1] + b1;
            float v2 = acc[mt][nt][2] + b0, v3 = acc[mt][nt][3] + b1;
            if (RES) {
                float2 q0 = *(const float2*)(Cin + (size_t)row0 * N + col);
                float2 q1 = *(const float2*)(Cin + (size_t)(row0 + 8) * N + col);
                v0 += q0.x; v1 += q0.y; v2 += q1.x; v3 += q1.y;
            }
            if (RELU) {
                v0 = fmaxf(v0, 0.f); v1 = fmaxf(v1, 0.f);
                v2 = fmaxf(v2, 0.f); v3 = fmaxf(v3, 0.f);
            }
            if (OP == 2 && col < HID) {
                v0 *= 0.125f; v1 *= 0.125f; v2 *= 0.125f; v3 *= 0.125f;
            }
            if (OP >= 1) {
                v0 = roundtf(v0); v1 = roundtf(v1);
                v2 = roundtf(v2); v3 = roundtf(v3);
            }
            *(float2*)(C + (size_t)row0 * N + col) = make_float2(v0, v1);
            *(float2*)(C + (size_t)(row0 + 8) * N + col) = make_float2(v2, v3);
        }
    }
}

// ============== tensor-core flash attention ==============
// qkv pre-rounded tf32, Q pre-scaled by 0.125 (in QKV GEMM epilogue).
#define AQS 68
#define AVS 72
#define AOQ 0
#define AOK 4352
#define AOV 8704
#define AOP 13312
#define AOM 17664
#define ATTN_SMEM ((17664 + 64) * 4)

__global__ void __launch_bounds__(128) attn_mma(const float* __restrict__ qkv,
                                                const int* __restrict__ src,
                                                float* __restrict__ O) {
    extern __shared__ float sa[];
    uint32_t* smu = (uint32_t*)sa;
    int bh = blockIdx.y;
    int b = bh >> 3, h = bh & 7;
    int q0 = blockIdx.x * 64;
    int tid = threadIdx.x;
    int lane = tid & 31, w = tid >> 5;
    int g = lane >> 2, tig = lane & 3;

    // load Q via cp.async (already tf32 + scaled)
    const float* Qg = qkv + (size_t)(b * SEQ + q0) * QKV_STR + h * HDD;
#pragma unroll
    for (int i = tid; i < 1024; i += 128) {
        int row = i >> 4, c4 = (i & 15) << 2;
        cp16(smem_u32(smu + AOQ + row * AQS + c4), Qg + (size_t)row * QKV_STR + c4);
    }
    CP_COMMIT();

    float o_acc[8][4];
#pragma unroll
    for (int nt = 0; nt < 8; nt++)
#pragma unroll
        for (int r = 0; r < 4; r++) o_acc[nt][r] = 0.f;
    float mr0 = -1e30f, mr1 = -1e30f, lr0 = 0.f, lr1 = 0.f;

    for (int kt = 0; kt < SEQ / 64; kt++) {
        __syncthreads();   // K/V/kmask reuse barrier
        const float* Kg = qkv + (size_t)(b * SEQ + kt * 64) * QKV_STR + HID + h * HDD;
        const float* Vg = Kg + HID;
#pragma unroll
        for (int i = tid; i < 1024; i += 128) {
            int row = i >> 4, c4 = (i & 15) << 2;
            cp16(smem_u32(smu + AOK + row * AQS + c4), Kg + (size_t)row * QKV_STR + c4);
            cp16(smem_u32(smu + AOV + row * AVS + c4), Vg + (size_t)row * QKV_STR + c4);
        }
        CP_COMMIT();
        if (tid < 64) sa[AOM + tid] = (src[b * SEQ + kt * 64 + tid] != 0) ? 0.f : -1e10f;
        CP_WAIT(0);
        __syncthreads();

        // stage 1: S = Q @ K^T
        float sc[8][4];
#pragma unroll
        for (int nt = 0; nt < 8; nt++)
#pragma unroll
            for (int r = 0; r < 4; r++) sc[nt][r] = 0.f;
#pragma unroll
        for (int kk = 0; kk < 8; kk++) {
            uint32_t a[4];
            int r0 = (w * 16 + g) * AQS + kk * 8 + tig;
            int r1 = (w * 16 + 8 + g) * AQS + kk * 8 + tig;
            a[0] = smu[AOQ + r0]; a[1] = smu[AOQ + r1];
            a[2] = smu[AOQ + r0 + 4]; a[3] = smu[AOQ + r1 + 4];
#pragma unroll
            for (int nt = 0; nt < 8; nt++) {
                uint32_t bb[2];
                int rb = (nt * 8 + g) * AQS + kk * 8 + tig;
                bb[0] = smu[AOK + rb]; bb[1] = smu[AOK + rb + 4];
                mma_tf32(sc[nt], a, bb);
            }
        }

        // online softmax
        float m0 = -1e30f, m1 = -1e30f;
#pragma unroll
        for (int nt = 0; nt < 8; nt++) {
            float k0 = sa[AOM + nt * 8 + tig * 2];
            float k1 = sa[AOM + nt * 8 + tig * 2 + 1];
            sc[nt][0] += k0; sc[nt][1] += k1;
            sc[nt][2] += k0; sc[nt][3] += k1;
            m0 = fmaxf(m0, fmaxf(sc[nt][0], sc[nt][1]));
            m1 = fmaxf(m1, fmaxf(sc[nt][2], sc[nt][3]));
        }
        m0 = fmaxf(m0, __shfl_xor_sync(0xffffffffu, m0, 1));
        m0 = fmaxf(m0, __shfl_xor_sync(0xffffffffu, m0, 2));
        m1 = fmaxf(m1, __shfl_xor_sync(0xffffffffu, m1, 1));
        m1 = fmaxf(m1, __shfl_xor_sync(0xffffffffu, m1, 2));
        float mn0 = fmaxf(mr0, m0), mn1 = fmaxf(mr1, m1);
        float s0 = __expf(mr0 - mn0), s1 = __expf(mr1 - mn1);
        mr0 = mn0; mr1 = mn1;
        float l0 = 0.f, l1 = 0.f;
        int pr0 = AOP + (w * 16 + g) * AQS + tig * 2;
        int pr1 = AOP + (w * 16 + 8 + g) * AQS + tig * 2;
#pragma unroll
        for (int nt = 0; nt < 8; nt++) {
            float p0 = __expf(sc[nt][0] - mn0);
            float p1 = __expf(sc[nt][1] - mn0);
            float p2 = __expf(sc[nt][2] - mn1);
            float p3 = __expf(sc[nt][3] - mn1);
            l0 += p0 + p1; l1 += p2 + p3;
            smu[pr0 + nt * 8] = f2tf(p0); smu[pr0 + nt * 8 + 1] = f2tf(p1);
            smu[pr1 + nt * 8] = f2tf(p2); smu[pr1 + nt * 8 + 1] = f2tf(p3);
        }
        l0 += __shfl_xor_sync(0xffffffffu, l0, 1);
        l0 += __shfl_xor_sync(0xffffffffu, l0, 2);
        l1 += __shfl_xor_sync(0xffffffffu, l1, 1);
        l1 += __shfl_xor_sync(0xffffffffu, l1, 2);
        lr0 = lr0 * s0 + l0;
        lr1 = lr1 * s1 + l1;
#pragma unroll
        for (int nt = 0; nt < 8; nt++) {
            o_acc[nt][0] *= s0; o_acc[nt][1] *= s0;
            o_acc[nt][2] *= s1; o_acc[nt][3] *= s1;
        }
        __syncwarp();

        // stage 2: O += P @ V
#pragma unroll
        for (int kk = 0; kk < 8; kk++) {
            uint32_t a[4];
            int r0 = (w * 16 + g) * AQS + kk * 8 + tig;
            int r1 = (w * 16 + 8 + g) * AQS + kk * 8 + tig;
            a[0] = smu[AOP + r0]; a[1] = smu[AOP + r1];
            a[2] = smu[AOP + r0 + 4]; a[3] = smu[AOP + r1 + 4];
#pragma unroll
            for (int nt = 0; nt < 8; nt++) {
                uint32_t bb[2];
                bb[0] = smu[AOV + (kk * 8 + tig) * AVS + nt * 8 + g];
                bb[1] = smu[AOV + (kk * 8 + tig + 4) * AVS + nt * 8 + g];
                mma_tf32(o_acc[nt], a, bb);
            }
        }
    }

    float i0 = 1.f / lr0, i1 = 1.f / lr1;
    int row0 = b * SEQ + q0 + w * 16 + g;
    float* Ob = O + (size_t)row0 * HID + h * HDD;
#pragma unroll
    for (int nt = 0; nt < 8; nt++) {
        *(float2*)(Ob + nt * 8 + tig * 2) =
            make_float2(roundtf(o_acc[nt][0] * i0), roundtf(o_acc[nt][1] * i0));
        *(float2*)(Ob + 8 * HID + nt * 8 + tig * 2) =
            make_float2(roundtf(o_acc[nt][2] * i1), roundtf(o_acc[nt][3] * i1));
    }
}

// ---------------- fused weight transposes (tf32-rounded) ----------------
#define NJOBS 14
struct TParams {
    const float* in[NJOBS];
    float* out[NJOBS];
    int R[NJOBS], C[NJOBS], tstart[NJOBS];
};
__global__ void transpose_all(TParams p) {
    __shared__ float t[32][33];
    int tile = blockIdx.x;
    int j = 0;
#pragma unroll
    for (int q = 1; q < NJOBS; q++)
        if (tile >= p.tstart[q]) j = q;
    int local = tile - p.tstart[j];
    int R = p.R[j], Cc = p.C[j];
    int tilesX = Cc >> 5;
    int c0 = (local % tilesX) * 32, r0 = (local / tilesX) * 32;
    const float* in = p.in[j];
    float* out = p.out[j];
    int x = threadIdx.x, y = threadIdx.y;
#pragma unroll
    for (int i = 0; i < 32; i += 8) t[y + i][x] = in[(size_t)(r0 + y + i) * Cc + c0 + x];
    __syncthreads();
#pragma unroll
    for (int i = 0; i < 32; i += 8)
        out[(size_t)(c0 + y + i) * R + r0 + x] = roundtf(t[x][y + i]);
}

// ---------------- bias concat (1536) ----------------
__global__ void concat_bias(const float* __restrict__ bq, const float* __restrict__ bk,
                            const float* __restrict__ bv, float* __restrict__ out) {
    int i = blockIdx.x * 256 + threadIdx.x;
    if (i < HID) out[i] = bq[i];
    else if (i < 2 * HID) out[i] = bk[i - HID];
    else out[i] = bv[i - 2 * HID];
}

// ---------------- block reduce (256 threads) ----------------
__device__ __forceinline__ float blockSum256(float v) {
    __shared__ float sh[8];
    int lane = threadIdx.x & 31, w = threadIdx.x >> 5;
#pragma unroll
    for (int o = 16; o; o >>= 1) v += __shfl_xor_sync(0xffffffffu, v, o);
    __syncthreads();
    if (lane == 0) sh[w] = v;
    __syncthreads();
    float r = sh[0];
#pragma unroll
    for (int i = 1; i < 8; i++) r += sh[i];
    return r;
}

// ---------------- embed + PE + time ----------------
__global__ void embed_kernel(const int* __restrict__ src,
                             const float* __restrict__ tint,
                             const float* __restrict__ emb,
                             const float* __restrict__ timeW,
                             const float* __restrict__ timeb,
                             float* __restrict__ x) {
    int n = blockIdx.x;
    int d = threadIdx.x;
    int s = n & (SEQ - 1);
    int v = src[n];
    float e = emb[(size_t)v * DIM + d];
    int i2 = (d >> 1) * 2;
    float div = expf((float)i2 * (-9.210340371976184f / (float)DIM));
    float ang = (float)s * div;
    float pe = (d & 1) ? cosf(ang) : sinf(ang);
    float tv = tint[n];
    x[n * DIM + d] = e + pe + tv * timeW[d] + timeb[d];
}

// ---------------- neighbor mean aggregation (tf32-rounded out) ----------------
__global__ void agg_kernel(const int* __restrict__ nidx,
                           const int* __restrict__ ncnt,
                           const float* __restrict__ x,
                           float* __restrict__ agg) {
    int n = blockIdx.x;
    int d = threadIdx.x;
    int cnt = ncnt[n];
    float sum = 0.f;
    for (int j = 0; j < cnt; j++) {
        int idx = nidx[n * NMAXN + j];
        sum += x[idx * DIM + d];
    }
    int dv = cnt > 1 ? cnt : 1;
    agg[n * DIM + d] = roundtf(sum / (float)dv);
}

// ---------------- soc LN + relu + select + x update ----------------
// writes x tf32-rounded (feeds proj GEMM), out_x full fp32 (output)
__global__ void soc_ln_kernel(const float* __restrict__ tmp,
                              const float* __restrict__ g,
                              const float* __restrict__ beta,
                              const int* __restrict__ ncnt,
                              const int* __restrict__ src,
                              float* __restrict__ x,
                              float* __restrict__ out_x) {
    int n = blockIdx.x;
    int d = threadIdx.x;
    float tv = tmp[n * DIM + d];
    float mu = blockSum256(tv) * (1.f / DIM);
    float df = tv - mu;
    float var = blockSum256(df * df) * (1.f / DIM);
    float y = df * rsqrtf(var + 1e-5f) * g[d] + beta[d];
    y = fmaxf(y, 0.f);
    float xv = x[n * DIM + d];
    float soc = (ncnt[n] > 0) ? y : xv;
    if (src[n] == 0) soc = 0.f;
    float xo = xv + 0.2f * soc;
    x[n * DIM + d] = roundtf(xo);
    out_x[n * DIM + d] = xo;
}

// ---------------- LayerNorm over 512 ----------------
__global__ void ln512_kernel(const float* __restrict__ in,
                             const float* __restrict__ g,
                             const float* __restrict__ b,
                             float* __restrict__ out, int round_out) {
    int n = blockIdx.x;
    int t = threadIdx.x;
    const float* r = in + (size_t)n * HID;
    float a0 = r[t], a1 = r[t + 256];
    float mu = blockSum256(a0 + a1) * (1.f / HID);
    float d0 = a0 - mu, d1 = a1 - mu;
    float var = blockSum256(d0 * d0 + d1 * d1) * (1.f / HID);
    float inv = rsqrtf(var + 1e-5f);
    float o0 = d0 * inv * g[t] + b[t];
    float o1 = d1 * inv * g[t + 256] + b[t + 256];
    if (round_out) { o0 = roundtf(o0); o1 = roundtf(o1); }
    out[(size_t)n * HID + t] = o0;
    out[(size_t)n * HID + t + 256] = o1;
}

// ---------------- host side ----------------
template <bool RELU, bool RES, int OP>
static void launch_gemm(const float* A, const float* Bt, const float* bias,
                        const float* Cin, float* C, int M, int Nn, int K) {
    dim3 grid(Nn / 128, M / 128);
    tc_gemm<RELU, RES, OP><<<grid, 256, GEMM_SMEM>>>(A, Bt, bias, Cin, C, M, Nn, K);
}

extern "C" void kernel_launch(void* const* d_in, const int* in_sizes, int n_in,
                              void* d_out, int out_size) {
    const int*   src   = (const int*)d_in[0];
    const int*   nidx  = (const int*)d_in[2];
    const int*   ncnt  = (const int*)d_in[3];
    const float* tint  = (const float*)d_in[4];
    const float* emb   = (const float*)d_in[5];
    const float* timeW = (const float*)d_in[6];
    const float* timeb = (const float*)d_in[7];
    const float* socW  = (const float*)d_in[8];
    const float* socb  = (const float*)d_in[9];
    const float* socg  = (const float*)d_in[10];
    const float* socbe = (const float*)d_in[11];
    const float* projW = (const float*)d_in[12];
    const float* projb = (const float*)d_in[13];
    const float* Wq    = (const float*)d_in[14];
    const float* bq    = (const float*)d_in[15];
    const float* Wk    = (const float*)d_in[16];
    const float* bk    = (const float*)d_in[17];
    const float* Wv    = (const float*)d_in[18];
    const float* bv    = (const float*)d_in[19];
    const float* Wo    = (const float*)d_in[20];
    const float* bo    = (const float*)d_in[21];
    const float* ln1g  = (const float*)d_in[22];
    const float* ln1b  = (const float*)d_in[23];
    const float* W1    = (const float*)d_in[24];
    const float* b1    = (const float*)d_in[25];
    const float* W2    = (const float*)d_in[26];
    const float* b2    = (const float*)d_in[27];
    const float* ln2g  = (const float*)d_in[28];
    const float* ln2b  = (const float*)d_in[29];

    float *x, *agg, *tmp, *h, *qkv, *o, *t1, *f1, *wt, *bqkv;
    void* p;
    cudaGetSymbolAddress(&p, g_x);    x    = (float*)p;
    cudaGetSymbolAddress(&p, g_agg);  agg  = (float*)p;
    cudaGetSymbolAddress(&p, g_tmp);  tmp  = (float*)p;
    cudaGetSymbolAddress(&p, g_h);    h    = (float*)p;
    cudaGetSymbolAddress(&p, g_qkv);  qkv  = (float*)p;
    cudaGetSymbolAddress(&p, g_o);    o    = (float*)p;
    cudaGetSymbolAddress(&p, g_t1);   t1   = (float*)p;
    cudaGetSymbolAddress(&p, g_f1);   f1   = (float*)p;
    cudaGetSymbolAddress(&p, g_wt);   wt   = (float*)p;
    cudaGetSymbolAddress(&p, g_bqkv); bqkv = (float*)p;

    cudaFuncSetAttribute(tc_gemm<false, true, 0>,  cudaFuncAttributeMaxDynamicSharedMemorySize, GEMM_SMEM);
    cudaFuncSetAttribute(tc_gemm<false, false, 1>, cudaFuncAttributeMaxDynamicSharedMemorySize, GEMM_SMEM);
    cudaFuncSetAttribute(tc_gemm<false, false, 2>, cudaFuncAttributeMaxDynamicSharedMemorySize, GEMM_SMEM);
    cudaFuncSetAttribute(tc_gemm<true, false, 1>,  cudaFuncAttributeMaxDynamicSharedMemorySize, GEMM_SMEM);
    cudaFuncSetAttribute(attn_mma, cudaFuncAttributeMaxDynamicSharedMemorySize, ATTN_SMEM);

    float* out_h = (float*)d_out;
    float* out_x = (float*)d_out + N_TOK * HID;

    // --- fused weight transposes (single launch, tf32-rounded) ---
    float* socT  = wt + WT_SOC;
    float* projT = wt + WT_PROJ;
    {
        TParams tp;
        int idx = 0, cum = 0;
        auto add = [&](const float* in, float* out, int R, int C) {
            tp.in[idx] = in; tp.out[idx] = out; tp.R[idx] = R; tp.C[idx] = C;
            tp.tstart[idx] = cum;
            cum += (R / 32) * (C / 32);
            idx++;
        };
        add(socW, socT, DIM, DIM);
        add(projW, projT, DIM, HID);
        for (int l = 0; l < 2; l++) {
            float* base = wt + WT_LAYER + (size_t)l * WT_PER_L;
            add(Wq + (size_t)l * HID * HID, base + L_QKV + 0 * 262144, HID, HID);
            add(Wk + (size_t)l * HID * HID, base + L_QKV + 1 * 262144, HID, HID);
            add(Wv + (size_t)l * HID * HID, base + L_QKV + 2 * 262144, HID, HID);
            add(Wo + (size_t)l * HID * HID, base + L_WO, HID, HID);
            add(W1 + (size_t)l * HID * PFF, base + L_W1, HID, PFF);
            add(W2 + (size_t)l * PFF * HID, base + L_W2, PFF, HID);
        }
        transpose_all<<<cum, dim3(32, 8)>>>(tp);
    }
    for (int l = 0; l < 2; l++)
        concat_bias<<<6, 256>>>(bq + l * HID, bk + l * HID, bv + l * HID, bqkv + l * QKV_STR);

    // front end
    embed_kernel<<<N_TOK, 256>>>(src, tint, emb, timeW, timeb, x);
    agg_kernel<<<N_TOK, 256>>>(nidx, ncnt, x, agg);
    launch_gemm<false, true, 0>(agg, socT, socb, x, tmp, N_TOK, DIM, DIM);
    soc_ln_kernel<<<N_TOK, 256>>>(tmp, socg, socbe, ncnt, src, x, out_x);
    launch_gemm<false, false, 1>(x, projT, projb, (const float*)0, h, N_TOK, HID, DIM);

    for (int l = 0; l < 2; l++) {
        float* base = wt + WT_LAYER + (size_t)l * WT_PER_L;
        // fused QKV (rounds output, scales Q cols by 1/8)
        launch_gemm<false, false, 2>(h, base + L_QKV, bqkv + l * QKV_STR, (const float*)0,
                                     qkv, N_TOK, QKV_STR, HID);
        attn_mma<<<dim3(SEQ / 64, BATCH * NHD), 128, ATTN_SMEM>>>(qkv, src, o);
        launch_gemm<false, true, 0>(o, base + L_WO, bo + l * HID, h, t1, N_TOK, HID, HID);
        ln512_kernel<<<N_TOK, 256>>>(t1, ln1g + l * HID, ln1b + l * HID, h, 1);
        launch_gemm<true, false, 1>(h, base + L_W1, b1 + l * PFF, (const float*)0, f1, N_TOK, PFF, HID);
        launch_gemm<false, true, 0>(f1, base + L_W2, b2 + l * HID, h, t1, N_TOK, HID, PFF);
        ln512_kernel<<<N_TOK, 256>>>(t1, ln2g + l * HID, ln2b + l * HID,
                                     (l == 1) ? out_h : h, (l == 1) ? 0 : 1);
    }
}

// round 6
// speedup vs baseline: 4.1049x; 1.0567x over previous
#include <cuda_runtime.h>
#include <math.h>
#include <stdint.h>

// Problem dims (fixed)
#define BATCH 32
#define SEQ   512
#define N_TOK (BATCH * SEQ)   // 16384
#define DIM   256
#define HID   512
#define PFF   2048
#define NHD   8
#define HDD   64
#define NMAXN 15
#define QKV_STR 1536

// ---------------- scratch (device globals: allocation-free) ----------------
__device__ float g_x[N_TOK * DIM];
__device__ float g_agg[N_TOK * DIM];
__device__ float g_tmp[N_TOK * DIM];
__device__ float g_h[N_TOK * HID];
__device__ float g_qkv[N_TOK * QKV_STR];
__device__ float g_o[N_TOK * HID];
__device__ float g_t1[N_TOK * HID];
__device__ float g_f1[N_TOK * PFF];
__device__ float g_bqkv[2 * QKV_STR];
#define WT_SOC   0
#define WT_PROJ  65536
#define WT_LAYER 196608
#define WT_PER_L 3145728
#define L_QKV 0
#define L_WO  786432
#define L_W1  1048576
#define L_W2  2097152
__device__ float g_wt[WT_LAYER + 2 * WT_PER_L];

// ======================= helpers =======================
__device__ __forceinline__ uint32_t smem_u32(const void* p) {
    uint32_t a;
    asm("{ .reg .u64 t; cvta.to.shared.u64 t, %1; cvt.u32.u64 %0, t; }" : "=r"(a) : "l"(p));
    return a;
}
__device__ __forceinline__ uint32_t f2tf(float f) {
    uint32_t u;
    asm("cvt.rna.tf32.f32 %0, %1;" : "=r"(u) : "f"(f));
    return u;
}
__device__ __forceinline__ float roundtf(float f) { return __uint_as_float(f2tf(f)); }
__device__ __forceinline__ void cp16(uint32_t dst, const void* src) {
    asm volatile("cp.async.cg.shared.global [%0], [%1], 16;" :: "r"(dst), "l"(src));
}
#define CP_COMMIT() asm volatile("cp.async.commit_group;" ::: "memory")
#define CP_WAIT(n)  asm volatile("cp.async.wait_group %0;" :: "n"(n) : "memory")

__device__ __forceinline__ void mma_tf32(float* c, const uint32_t* a, const uint32_t* b) {
    asm volatile(
        "mma.sync.aligned.m16n8k8.row.col.f32.tf32.tf32.f32 "
        "{%0,%1,%2,%3}, {%4,%5,%6,%7}, {%8,%9}, {%0,%1,%2,%3};\n"
        : "+f"(c[0]), "+f"(c[1]), "+f"(c[2]), "+f"(c[3])
        : "r"(a[0]), "r"(a[1]), "r"(a[2]), "r"(a[3]), "r"(b[0]), "r"(b[1]));
}

// Smem geometry: per stage As[128][36] + Bs[128][36] floats
#define TSTRIDE 36
#define STAGE_F (2 * 128 * TSTRIDE)
#define GEMM_SMEM (2 * STAGE_F * 4)

// ============== tf32 tensor-core GEMM ==============
// 128x128 CTA tile, BK=32, 128 threads (4 warps = 2x2), warp tile 64x64.
// All A/B operands PRE-ROUNDED tf32 in gmem -> raw smem loads.
// OP: 0 = plain store, 1 = tf32-rounded, 2 = tf32-rounded + scale cols<HID by 0.125
template <bool RELU, bool RES, int OP>
__global__ void __launch_bounds__(128) tc_gemm(const float* __restrict__ A,
                                               const float* __restrict__ Bt,
                                               const float* __restrict__ bias,
                                               const float* __restrict__ Cin,
                                               float* __restrict__ C,
                                               int M, int N, int K) {
    extern __shared__ float sm[];
    int tid = threadIdx.x;
    int m0 = blockIdx.y * 128, n0 = blockIdx.x * 128;
    int lane = tid & 31, wid = tid >> 5;
    int wm = wid & 1, wn = wid >> 1;     // warp tile: rows wm*64, cols wn*64
    int g = lane >> 2, tig = lane & 3;
    uint32_t sb = smem_u32(sm);

    float acc[4][8][4];
#pragma unroll
    for (int mt = 0; mt < 4; mt++)
#pragma unroll
        for (int nt = 0; nt < 8; nt++)
#pragma unroll
            for (int r = 0; r < 4; r++) acc[mt][nt][r] = 0.f;

    int nk = K >> 5;
    int lrow = tid >> 3, lc4 = (tid & 7) * 4;   // 16 rows per pass, 8 passes

    auto issue = [&](int s, int i) {
#pragma unroll
        for (int p = 0; p < 8; p++) {
            int row = lrow + p * 16;
            uint32_t da = sb + (uint32_t)((s * STAGE_F + row * TSTRIDE + lc4) * 4);
            uint32_t db = da + (uint32_t)(128 * TSTRIDE * 4);
            cp16(da, A + (size_t)(m0 + row) * K + i * 32 + lc4);
            cp16(db, Bt + (size_t)(n0 + row) * K + i * 32 + lc4);
        }
        CP_COMMIT();
    };

    issue(0, 0);
    for (int i = 0; i < nk; i++) {
        int s = i & 1;
        if (i + 1 < nk) {
            issue(s ^ 1, i + 1);
            CP_WAIT(1);
        } else {
            CP_WAIT(0);
        }
        __syncthreads();
        const uint32_t* As = (const uint32_t*)(sm + s * STAGE_F);
        const uint32_t* Bs = As + 128 * TSTRIDE;
#pragma unroll
        for (int kk = 0; kk < 4; kk++) {
            int k = kk * 8 + tig;
            uint32_t af[4][4], bf[8][2];
#pragma unroll
            for (int mt = 0; mt < 4; mt++) {
                int m = wm * 64 + mt * 16 + g;
                af[mt][0] = As[m * TSTRIDE + k];
                af[mt][1] = As[(m + 8) * TSTRIDE + k];
                af[mt][2] = As[m * TSTRIDE + k + 4];
                af[mt][3] = As[(m + 8) * TSTRIDE + k + 4];
            }
#pragma unroll
            for (int nt = 0; nt < 8; nt++) {
                int n = wn * 64 + nt * 8 + g;
                bf[nt][0] = Bs[n * TSTRIDE + k];
                bf[nt][1] = Bs[n * TSTRIDE + k + 4];
            }
#pragma unroll
            for (int mt = 0; mt < 4; mt++)
#pragma unroll
                for (int nt = 0; nt < 8; nt++)
                    mma_tf32(acc[mt][nt], af[mt], bf[nt]);
        }
        __syncthreads();
    }

#pragma unroll
    for (int mt = 0; mt < 4; mt++) {
#pragma unroll
        for (int nt = 0; nt < 8; nt++) {
            int row0 = m0 + wm * 64 + mt * 16 + g;
            int col = n0 + wn * 64 + nt * 8 + tig * 2;
            float b0 = __ldg(&bias[col]), b1 = __ldg(&bias[col + 1]);
            float v0 = acc[mt][nt][0] + b0, v1 = acc[mt][nt][1] + b1;
            float v2 = acc[mt][nt][2] + b0, v3 = acc[mt][nt][3] + b1;
            if (RES) {
                float2 q0 = *(const float2*)(Cin + (size_t)row0 * N + col);
                float2 q1 = *(const float2*)(Cin + (size_t)(row0 + 8) * N + col);
                v0 += q0.x; v1 += q0.y; v2 += q1.x; v3 += q1.y;
            }
            if (RELU) {
                v0 = fmaxf(v0, 0.f); v1 = fmaxf(v1, 0.f);
                v2 = fmaxf(v2, 0.f); v3 = fmaxf(v3, 0.f);
            }
            if (OP == 2 && col < HID) {
                v0 *= 0.125f; v1 *= 0.125f; v2 *= 0.125f; v3 *= 0.125f;
            }
            if (OP >= 1) {
                v0 = roundtf(v0); v1 = roundtf(v1);
                v2 = roundtf(v2); v3 = roundtf(v3);
            }
            *(float2*)(C + (size_t)row0 * N + col) = make_float2(v0, v1);
            *(float2*)(C + (size_t)(row0 + 8) * N + col) = make_float2(v2, v3);
        }
    }
}

// ============== tensor-core flash attention (BQ=128, BK=64) ==============
// 256 threads = 8 warps x 16 q-rows. qkv pre-rounded tf32, Q pre-scaled 0.125.
// smem floats: Q[128][68] K[64][68] V[64][72] P[128][68] kmask[64]
#define AQS 68
#define AVS 72
#define AOQ 0
#define AOK 8704
#define AOV 13056
#define AOP 17664
#define AOM 26368
#define ATTN_SMEM ((26368 + 64) * 4)

__global__ void __launch_bounds__(256) attn_mma(const float* __restrict__ qkv,
                                                const int* __restrict__ src,
                                                float* __restrict__ O) {
    extern __shared__ float sa[];
    uint32_t* smu = (uint32_t*)sa;
    int bh = blockIdx.y;
    int b = bh >> 3, h = bh & 7;
    int q0 = blockIdx.x * 128;
    int tid = threadIdx.x;
    int lane = tid & 31, w = tid >> 5;
    int g = lane >> 2, tig = lane & 3;

    // load Q via cp.async (already tf32 + scaled): 128 rows
    const float* Qg = qkv + (size_t)(b * SEQ + q0) * QKV_STR + h * HDD;
#pragma unroll
    for (int i = tid; i < 2048; i += 256) {
        int row = i >> 4, c4 = (i & 15) << 2;
        cp16(smem_u32(smu + AOQ + row * AQS + c4), Qg + (size_t)row * QKV_STR + c4);
    }
    CP_COMMIT();

    float o_acc[8][4];
#pragma unroll
    for (int nt = 0; nt < 8; nt++)
#pragma unroll
        for (int r = 0; r < 4; r++) o_acc[nt][r] = 0.f;
    float mr0 = -1e30f, mr1 = -1e30f, lr0 = 0.f, lr1 = 0.f;

    for (int kt = 0; kt < SEQ / 64; kt++) {
        __syncthreads();   // K/V/kmask reuse barrier
        const float* Kg = qkv + (size_t)(b * SEQ + kt * 64) * QKV_STR + HID + h * HDD;
        const float* Vg = Kg + HID;
#pragma unroll
        for (int i = tid; i < 1024; i += 256) {
            int row = i >> 4, c4 = (i & 15) << 2;
            cp16(smem_u32(smu + AOK + row * AQS + c4), Kg + (size_t)row * QKV_STR + c4);
            cp16(smem_u32(smu + AOV + row * AVS + c4), Vg + (size_t)row * QKV_STR + c4);
        }
        CP_COMMIT();
        if (tid < 64) sa[AOM + tid] = (src[b * SEQ + kt * 64 + tid] != 0) ? 0.f : -1e10f;
        CP_WAIT(0);
        __syncthreads();

        // stage 1: S = Q @ K^T  (per warp: rows w*16..+15, all 64 cols)
        float sc[8][4];
#pragma unroll
        for (int nt = 0; nt < 8; nt++)
#pragma unroll
            for (int r = 0; r < 4; r++) sc[nt][r] = 0.f;
#pragma unroll
        for (int kk = 0; kk < 8; kk++) {
            uint32_t a[4];
            int r0 = (w * 16 + g) * AQS + kk * 8 + tig;
            int r1 = (w * 16 + 8 + g) * AQS + kk * 8 + tig;
            a[0] = smu[AOQ + r0]; a[1] = smu[AOQ + r1];
            a[2] = smu[AOQ + r0 + 4]; a[3] = smu[AOQ + r1 + 4];
#pragma unroll
            for (int nt = 0; nt < 8; nt++) {
                uint32_t bb[2];
                int rb = (nt * 8 + g) * AQS + kk * 8 + tig;
                bb[0] = smu[AOK + rb]; bb[1] = smu[AOK + rb + 4];
                mma_tf32(sc[nt], a, bb);
            }
        }

        // online softmax
        float m0 = -1e30f, m1 = -1e30f;
#pragma unroll
        for (int nt = 0; nt < 8; nt++) {
            float k0 = sa[AOM + nt * 8 + tig * 2];
            float k1 = sa[AOM + nt * 8 + tig * 2 + 1];
            sc[nt][0] += k0; sc[nt][1] += k1;
            sc[nt][2] += k0; sc[nt][3] += k1;
            m0 = fmaxf(m0, fmaxf(sc[nt][0], sc[nt][1]));
            m1 = fmaxf(m1, fmaxf(sc[nt][2], sc[nt][3]));
        }
        m0 = fmaxf(m0, __shfl_xor_sync(0xffffffffu, m0, 1));
        m0 = fmaxf(m0, __shfl_xor_sync(0xffffffffu, m0, 2));
        m1 = fmaxf(m1, __shfl_xor_sync(0xffffffffu, m1, 1));
        m1 = fmaxf(m1, __shfl_xor_sync(0xffffffffu, m1, 2));
        float mn0 = fmaxf(mr0, m0), mn1 = fmaxf(mr1, m1);
        float s0 = __expf(mr0 - mn0), s1 = __expf(mr1 - mn1);
        mr0 = mn0; mr1 = mn1;
        float l0 = 0.f, l1 = 0.f;
        int pr0 = AOP + (w * 16 + g) * AQS + tig * 2;
        int pr1 = AOP + (w * 16 + 8 + g) * AQS + tig * 2;
#pragma unroll
        for (int nt = 0; nt < 8; nt++) {
            float p0 = __expf(sc[nt][0] - mn0);
            float p1 = __expf(sc[nt][1] - mn0);
            float p2 = __expf(sc[nt][2] - mn1);
            float p3 = __expf(sc[nt][3] - mn1);
            l0 += p0 + p1; l1 += p2 + p3;
            smu[pr0 + nt * 8] = f2tf(p0); smu[pr0 + nt * 8 + 1] = f2tf(p1);
            smu[pr1 + nt * 8] = f2tf(p2); smu[pr1 + nt * 8 + 1] = f2tf(p3);
        }
        l0 += __shfl_xor_sync(0xffffffffu, l0, 1);
        l0 += __shfl_xor_sync(0xffffffffu, l0, 2);
        l1 += __shfl_xor_sync(0xffffffffu, l1, 1);
        l1 += __shfl_xor_sync(0xffffffffu, l1, 2);
        lr0 = lr0 * s0 + l0;
        lr1 = lr1 * s1 + l1;
#pragma unroll
        for (int nt = 0; nt < 8; nt++) {
            o_acc[nt][0] *= s0; o_acc[nt][1] *= s0;
            o_acc[nt][2] *= s1; o_acc[nt][3] *= s1;
        }
        __syncwarp();   // P written/read by this warp only

        // stage 2: O += P @ V
#pragma unroll
        for (int kk = 0; kk < 8; kk++) {
            uint32_t a[4];
            int r0 = (w * 16 + g) * AQS + kk * 8 + tig;
            int r1 = (w * 16 + 8 + g) * AQS + kk * 8 + tig;
            a[0] = smu[AOP + r0]; a[1] = smu[AOP + r1];
            a[2] = smu[AOP + r0 + 4]; a[3] = smu[AOP + r1 + 4];
#pragma unroll
            for (int nt = 0; nt < 8; nt++) {
                uint32_t bb[2];
                bb[0] = smu[AOV + (kk * 8 + tig) * AVS + nt * 8 + g];
                bb[1] = smu[AOV + (kk * 8 + tig + 4) * AVS + nt * 8 + g];
                mma_tf32(o_acc[nt], a, bb);
            }
        }
    }

    float i0 = 1.f / lr0, i1 = 1.f / lr1;
    int row0 = b * SEQ + q0 + w * 16 + g;
    float* Ob = O + (size_t)row0 * HID + h * HDD;
#pragma unroll
    for (int nt = 0; nt < 8; nt++) {
        *(float2*)(Ob + nt * 8 + tig * 2) =
            make_float2(roundtf(o_acc[nt][0] * i0), roundtf(o_acc[nt][1] * i0));
        *(float2*)(Ob + 8 * HID + nt * 8 + tig * 2) =
            make_float2(roundtf(o_acc[nt][2] * i1), roundtf(o_acc[nt][3] * i1));
    }
}

// ---------------- fused weight transposes (tf32-rounded) ----------------
#define NJOBS 14
struct TParams {
    const float* in[NJOBS];
    float* out[NJOBS];
    int R[NJOBS], C[NJOBS], tstart[NJOBS];
};
__global__ void transpose_all(TParams p) {
    __shared__ float t[32][33];
    int tile = blockIdx.x;
    int j = 0;
#pragma unroll
    for (int q = 1; q < NJOBS; q++)
        if (tile >= p.tstart[q]) j = q;
    int local = tile - p.tstart[j];
    int R = p.R[j], Cc = p.C[j];
    int tilesX = Cc >> 5;
    int c0 = (local % tilesX) * 32, r0 = (local / tilesX) * 32;
    const float* in = p.in[j];
    float* out = p.out[j];
    int x = threadIdx.x, y = threadIdx.y;
#pragma unroll
    for (int i = 0; i < 32; i += 8) t[y + i][x] = in[(size_t)(r0 + y + i) * Cc + c0 + x];
    __syncthreads();
#pragma unroll
    for (int i = 0; i < 32; i += 8)
        out[(size_t)(c0 + y + i) * R + r0 + x] = roundtf(t[x][y + i]);
}

// ---------------- bias concat (1536) ----------------
__global__ void concat_bias(const float* __restrict__ bq, const float* __restrict__ bk,
                            const float* __restrict__ bv, float* __restrict__ out) {
    int i = blockIdx.x * 256 + threadIdx.x;
    if (i < HID) out[i] = bq[i];
    else if (i < 2 * HID) out[i] = bk[i - HID];
    else out[i] = bv[i - 2 * HID];
}

// ---------------- block reduce (256 threads) ----------------
__device__ __forceinline__ float blockSum256(float v) {
    __shared__ float sh[8];
    int lane = threadIdx.x & 31, w = threadIdx.x >> 5;
#pragma unroll
    for (int o = 16; o; o >>= 1) v += __shfl_xor_sync(0xffffffffu, v, o);
    __syncthreads();
    if (lane == 0) sh[w] = v;
    __syncthreads();
    float r = sh[0];
#pragma unroll
    for (int i = 1; i < 8; i++) r += sh[i];
    return r;
}

// ---------------- embed + PE + time ----------------
__global__ void embed_kernel(const int* __restrict__ src,
                             const float* __restrict__ tint,
                             const float* __restrict__ emb,
                             const float* __restrict__ timeW,
                             const float* __restrict__ timeb,
                             float* __restrict__ x) {
    int n = blockIdx.x;
    int d = threadIdx.x;
    int s = n & (SEQ - 1);
    int v = src[n];
    float e = emb[(size_t)v * DIM + d];
    int i2 = (d >> 1) * 2;
    float div = expf((float)i2 * (-9.210340371976184f / (float)DIM));
    float ang = (float)s * div;
    float pe = (d & 1) ? cosf(ang) : sinf(ang);
    float tv = tint[n];
    x[n * DIM + d] = e + pe + tv * timeW[d] + timeb[d];
}

// ---------------- neighbor mean aggregation (tf32-rounded out) ----------------
__global__ void agg_kernel(const int* __restrict__ nidx,
                           const int* __restrict__ ncnt,
                           const float* __restrict__ x,
                           float* __restrict__ agg) {
    int n = blockIdx.x;
    int d = threadIdx.x;
    int cnt = ncnt[n];
    float sum = 0.f;
    for (int j = 0; j < cnt; j++) {
        int idx = nidx[n * NMAXN + j];
        sum += x[idx * DIM + d];
    }
    int dv = cnt > 1 ? cnt : 1;
    agg[n * DIM + d] = roundtf(sum / (float)dv);
}

// ---------------- soc LN + relu + select + x update ----------------
__global__ void soc_ln_kernel(const float* __restrict__ tmp,
                              const float* __restrict__ g,
                              const float* __restrict__ beta,
                              const int* __restrict__ ncnt,
                              const int* __restrict__ src,
                              float* __restrict__ x,
                              float* __restrict__ out_x) {
    int n = blockIdx.x;
    int d = threadIdx.x;
    float tv = tmp[n * DIM + d];
    float mu = blockSum256(tv) * (1.f / DIM);
    float df = tv - mu;
    float var = blockSum256(df * df) * (1.f / DIM);
    float y = df * rsqrtf(var + 1e-5f) * g[d] + beta[d];
    y = fmaxf(y, 0.f);
    float xv = x[n * DIM + d];
    float soc = (ncnt[n] > 0) ? y : xv;
    if (src[n] == 0) soc = 0.f;
    float xo = xv + 0.2f * soc;
    x[n * DIM + d] = roundtf(xo);
    out_x[n * DIM + d] = xo;
}

// ---------------- LayerNorm over 512 ----------------
__global__ void ln512_kernel(const float* __restrict__ in,
                             const float* __restrict__ g,
                             const float* __restrict__ b,
                             float* __restrict__ out, int round_out) {
    int n = blockIdx.x;
    int t = threadIdx.x;
    const float* r = in + (size_t)n * HID;
    float a0 = r[t], a1 = r[t + 256];
    float mu = blockSum256(a0 + a1) * (1.f / HID);
    float d0 = a0 - mu, d1 = a1 - mu;
    float var = blockSum256(d0 * d0 + d1 * d1) * (1.f / HID);
    float inv = rsqrtf(var + 1e-5f);
    float o0 = d0 * inv * g[t] + b[t];
    float o1 = d1 * inv * g[t + 256] + b[t + 256];
    if (round_out) { o0 = roundtf(o0); o1 = roundtf(o1); }
    out[(size_t)n * HID + t] = o0;
    out[(size_t)n * HID + t + 256] = o1;
}

// ---------------- host side ----------------
template <bool RELU, bool RES, int OP>
static void launch_gemm(const float* A, const float* Bt, const float* bias,
                        const float* Cin, float* C, int M, int Nn, int K) {
    dim3 grid(Nn / 128, M / 128);
    tc_gemm<RELU, RES, OP><<<grid, 128, GEMM_SMEM>>>(A, Bt, bias, Cin, C, M, Nn, K);
}

extern "C" void kernel_launch(void* const* d_in, const int* in_sizes, int n_in,
                              void* d_out, int out_size) {
    const int*   src   = (const int*)d_in[0];
    const int*   nidx  = (const int*)d_in[2];
    const int*   ncnt  = (const int*)d_in[3];
    const float* tint  = (const float*)d_in[4];
    const float* emb   = (const float*)d_in[5];
    const float* timeW = (const float*)d_in[6];
    const float* timeb = (const float*)d_in[7];
    const float* socW  = (const float*)d_in[8];
    const float* socb  = (const float*)d_in[9];
    const float* socg  = (const float*)d_in[10];
    const float* socbe = (const float*)d_in[11];
    const float* projW = (const float*)d_in[12];
    const float* projb = (const float*)d_in[13];
    const float* Wq    = (const float*)d_in[14];
    const float* bq    = (const float*)d_in[15];
    const float* Wk    = (const float*)d_in[16];
    const float* bk    = (const float*)d_in[17];
    const float* Wv    = (const float*)d_in[18];
    const float* bv    = (const float*)d_in[19];
    const float* Wo    = (const float*)d_in[20];
    const float* bo    = (const float*)d_in[21];
    const float* ln1g  = (const float*)d_in[22];
    const float* ln1b  = (const float*)d_in[23];
    const float* W1    = (const float*)d_in[24];
    const float* b1    = (const float*)d_in[25];
    const float* W2    = (const float*)d_in[26];
    const float* b2    = (const float*)d_in[27];
    const float* ln2g  = (const float*)d_in[28];
    const float* ln2b  = (const float*)d_in[29];

    float *x, *agg, *tmp, *h, *qkv, *o, *t1, *f1, *wt, *bqkv;
    void* p;
    cudaGetSymbolAddress(&p, g_x);    x    = (float*)p;
    cudaGetSymbolAddress(&p, g_agg);  agg  = (float*)p;
    cudaGetSymbolAddress(&p, g_tmp);  tmp  = (float*)p;
    cudaGetSymbolAddress(&p, g_h);    h    = (float*)p;
    cudaGetSymbolAddress(&p, g_qkv);  qkv  = (float*)p;
    cudaGetSymbolAddress(&p, g_o);    o    = (float*)p;
    cudaGetSymbolAddress(&p, g_t1);   t1   = (float*)p;
    cudaGetSymbolAddress(&p, g_f1);   f1   = (float*)p;
    cudaGetSymbolAddress(&p, g_wt);   wt   = (float*)p;
    cudaGetSymbolAddress(&p, g_bqkv); bqkv = (float*)p;

    cudaFuncSetAttribute(tc_gemm<false, true, 0>,  cudaFuncAttributeMaxDynamicSharedMemorySize, GEMM_SMEM);
    cudaFuncSetAttribute(tc_gemm<false, false, 1>, cudaFuncAttributeMaxDynamicSharedMemorySize, GEMM_SMEM);
    cudaFuncSetAttribute(tc_gemm<false, false, 2>, cudaFuncAttributeMaxDynamicSharedMemorySize, GEMM_SMEM);
    cudaFuncSetAttribute(tc_gemm<true, false, 1>,  cudaFuncAttributeMaxDynamicSharedMemorySize, GEMM_SMEM);
    cudaFuncSetAttribute(attn_mma, cudaFuncAttributeMaxDynamicSharedMemorySize, ATTN_SMEM);

    float* out_h = (float*)d_out;
    float* out_x = (float*)d_out + N_TOK * HID;

    // --- fused weight transposes (single launch, tf32-rounded) ---
    float* socT  = wt + WT_SOC;
    float* projT = wt + WT_PROJ;
    {
        TParams tp;
        int idx = 0, cum = 0;
        auto add = [&](const float* in, float* out, int R, int C) {
            tp.in[idx] = in; tp.out[idx] = out; tp.R[idx] = R; tp.C[idx] = C;
            tp.tstart[idx] = cum;
            cum += (R / 32) * (C / 32);
            idx++;
        };
        add(socW, socT, DIM, DIM);
        add(projW, projT, DIM, HID);
        for (int l = 0; l < 2; l++) {
            float* base = wt + WT_LAYER + (size_t)l * WT_PER_L;
            add(Wq + (size_t)l * HID * HID, base + L_QKV + 0 * 262144, HID, HID);
            add(Wk + (size_t)l * HID * HID, base + L_QKV + 1 * 262144, HID, HID);
            add(Wv + (size_t)l * HID * HID, base + L_QKV + 2 * 262144, HID, HID);
            add(Wo + (size_t)l * HID * HID, base + L_WO, HID, HID);
            add(W1 + (size_t)l * HID * PFF, base + L_W1, HID, PFF);
            add(W2 + (size_t)l * PFF * HID, base + L_W2, PFF, HID);
        }
        transpose_all<<<cum, dim3(32, 8)>>>(tp);
    }
    for (int l = 0; l < 2; l++)
        concat_bias<<<6, 256>>>(bq + l * HID, bk + l * HID, bv + l * HID, bqkv + l * QKV_STR);

    // front end
    embed_kernel<<<N_TOK, 256>>>(src, tint, emb, timeW, timeb, x);
    agg_kernel<<<N_TOK, 256>>>(nidx, ncnt, x, agg);
    launch_gemm<false, true, 0>(agg, socT, socb, x, tmp, N_TOK, DIM, DIM);
    soc_ln_kernel<<<N_TOK, 256>>>(tmp, socg, socbe, ncnt, src, x, out_x);
    launch_gemm<false, false, 1>(x, projT, projb, (const float*)0, h, N_TOK, HID, DIM);

    for (int l = 0; l < 2; l++) {
        float* base = wt + WT_LAYER + (size_t)l * WT_PER_L;
        // fused QKV (rounds output, scales Q cols by 1/8)
        launch_gemm<false, false, 2>(h, base + L_QKV, bqkv + l * QKV_STR, (const float*)0,
                                     qkv, N_TOK, QKV_STR, HID);
        attn_mma<<<dim3(SEQ / 128, BATCH * NHD), 256, ATTN_SMEM>>>(qkv, src, o);
        launch_gemm<false, true, 0>(o, base + L_WO, bo + l * HID, h, t1, N_TOK, HID, HID);
        ln512_kernel<<<N_TOK, 256>>>(t1, ln1g + l * HID, ln1b + l * HID, h, 1);
        launch_gemm<true, false, 1>(h, base + L_W1, b1 + l * PFF, (const float*)0, f1, N_TOK, PFF, HID);
        launch_gemm<false, true, 0>(f1, base + L_W2, b2 + l * HID, h, t1, N_TOK, HID, PFF);
        ln512_kernel<<<N_TOK, 256>>>(t1, ln2g + l * HID, ln2b + l * HID,
                                     (l == 1) ? out_h : h, (l == 1) ? 0 : 1);
    }
}

// round 7
// speedup vs baseline: 4.1573x; 1.0128x over previous
#include <cuda_runtime.h>
#include <math.h>
#include <stdint.h>

// Problem dims (fixed)
#define BATCH 32
#define SEQ   512
#define N_TOK (BATCH * SEQ)   // 16384
#define DIM   256
#define HID   512
#define PFF   2048
#define NHD   8
#define HDD   64
#define NMAXN 15
#define QKV_STR 1536

// ---------------- scratch (device globals: allocation-free) ----------------
__device__ float g_x[N_TOK * DIM];
__device__ float g_agg[N_TOK * DIM];
__device__ float g_tmp[N_TOK * DIM];
__device__ float g_h[N_TOK * HID];
__device__ float g_qkv[N_TOK * QKV_STR];
__device__ float g_o[N_TOK * HID];
__device__ float g_t1[N_TOK * HID];
__device__ float g_f1[N_TOK * PFF];
__device__ float g_bqkv[2 * QKV_STR];
#define WT_SOC   0
#define WT_PROJ  65536
#define WT_LAYER 196608
#define WT_PER_L 3145728
#define L_QKV 0
#define L_WO  786432
#define L_W1  1048576
#define L_W2  2097152
__device__ float g_wt[WT_LAYER + 2 * WT_PER_L];

// ======================= helpers =======================
__device__ __forceinline__ uint32_t smem_u32(const void* p) {
    uint32_t a;
    asm("{ .reg .u64 t; cvta.to.shared.u64 t, %1; cvt.u32.u64 %0, t; }" : "=r"(a) : "l"(p));
    return a;
}
__device__ __forceinline__ uint32_t f2tf(float f) {
    uint32_t u;
    asm("cvt.rna.tf32.f32 %0, %1;" : "=r"(u) : "f"(f));
    return u;
}
__device__ __forceinline__ float roundtf(float f) { return __uint_as_float(f2tf(f)); }
__device__ __forceinline__ void cp16(uint32_t dst, const void* src) {
    asm volatile("cp.async.cg.shared.global [%0], [%1], 16;" :: "r"(dst), "l"(src));
}
#define CP_COMMIT() asm volatile("cp.async.commit_group;" ::: "memory")
#define CP_WAIT(n)  asm volatile("cp.async.wait_group %0;" :: "n"(n) : "memory")

__device__ __forceinline__ void mma_tf32(float* c, const uint32_t* a, const uint32_t* b) {
    asm volatile(
        "mma.sync.aligned.m16n8k8.row.col.f32.tf32.tf32.f32 "
        "{%0,%1,%2,%3}, {%4,%5,%6,%7}, {%8,%9}, {%0,%1,%2,%3};\n"
        : "+f"(c[0]), "+f"(c[1]), "+f"(c[2]), "+f"(c[3])
        : "r"(a[0]), "r"(a[1]), "r"(a[2]), "r"(a[3]), "r"(b[0]), "r"(b[1]));
}
__device__ __forceinline__ float warpSum(float v) {
#pragma unroll
    for (int o = 16; o; o >>= 1) v += __shfl_xor_sync(0xffffffffu, v, o);
    return v;
}

// Smem geometry: per stage As[128][36] + Bs[128][36] floats
#define TSTRIDE 36
#define STAGE_F (2 * 128 * TSTRIDE)
#define GEMM_SMEM (2 * STAGE_F * 4)

// ============== tf32 tensor-core GEMM ==============
// 128x128 CTA tile, BK=32, 128 threads (4 warps = 2x2), warp tile 64x64.
// Single __syncthreads per K-tile (cp.async issued AFTER the barrier).
// OP: 0 = plain store, 1 = tf32-rounded, 2 = tf32-rounded + scale cols<HID by 0.125
template <bool RELU, bool RES, int OP>
__global__ void __launch_bounds__(128) tc_gemm(const float* __restrict__ A,
                                               const float* __restrict__ Bt,
                                               const float* __restrict__ bias,
                                               const float* __restrict__ Cin,
                                               float* __restrict__ C,
                                               int M, int N, int K) {
    extern __shared__ float sm[];
    int tid = threadIdx.x;
    int m0 = blockIdx.y * 128, n0 = blockIdx.x * 128;
    int lane = tid & 31, wid = tid >> 5;
    int wm = wid & 1, wn = wid >> 1;
    int g = lane >> 2, tig = lane & 3;
    uint32_t sb = smem_u32(sm);

    float acc[4][8][4];
#pragma unroll
    for (int mt = 0; mt < 4; mt++)
#pragma unroll
        for (int nt = 0; nt < 8; nt++)
#pragma unroll
            for (int r = 0; r < 4; r++) acc[mt][nt][r] = 0.f;

    int nk = K >> 5;
    int lrow = tid >> 3, lc4 = (tid & 7) * 4;

    auto issue = [&](int s, int i) {
#pragma unroll
        for (int p = 0; p < 8; p++) {
            int row = lrow + p * 16;
            uint32_t da = sb + (uint32_t)((s * STAGE_F + row * TSTRIDE + lc4) * 4);
            uint32_t db = da + (uint32_t)(128 * TSTRIDE * 4);
            cp16(da, A + (size_t)(m0 + row) * K + i * 32 + lc4);
            cp16(db, Bt + (size_t)(n0 + row) * K + i * 32 + lc4);
        }
        CP_COMMIT();
    };

    issue(0, 0);
    for (int i = 0; i < nk; i++) {
        int s = i & 1;
        CP_WAIT(0);
        __syncthreads();          // tile i visible; everyone done reading stage s^1
        if (i + 1 < nk) issue(s ^ 1, i + 1);   // safe: after barrier
        const uint32_t* As = (const uint32_t*)(sm + s * STAGE_F);
        const uint32_t* Bs = As + 128 * TSTRIDE;
#pragma unroll
        for (int kk = 0; kk < 4; kk++) {
            int k = kk * 8 + tig;
            uint32_t af[4][4], bf[8][2];
#pragma unroll
            for (int mt = 0; mt < 4; mt++) {
                int m = wm * 64 + mt * 16 + g;
                af[mt][0] = As[m * TSTRIDE + k];
                af[mt][1] = As[(m + 8) * TSTRIDE + k];
                af[mt][2] = As[m * TSTRIDE + k + 4];
                af[mt][3] = As[(m + 8) * TSTRIDE + k + 4];
            }
#pragma unroll
            for (int nt = 0; nt < 8; nt++) {
                int n = wn * 64 + nt * 8 + g;
                bf[nt][0] = Bs[n * TSTRIDE + k];
                bf[nt][1] = Bs[n * TSTRIDE + k + 4];
            }
#pragma unroll
            for (int mt = 0; mt < 4; mt++)
#pragma unroll
                for (int nt = 0; nt < 8; nt++)
                    mma_tf32(acc[mt][nt], af[mt], bf[nt]);
        }
    }

#pragma unroll
    for (int mt = 0; mt < 4; mt++) {
#pragma unroll
        for (int nt = 0; nt < 8; nt++) {
            int row0 = m0 + wm * 64 + mt * 16 + g;
            int col = n0 + wn * 64 + nt * 8 + tig * 2;
            float b0 = __ldg(&bias[col]), b1 = __ldg(&bias[col + 1]);
            float v0 = acc[mt][nt][0] + b0, v1 = acc[mt][nt][1] + b1;
            float v2 = acc[mt][nt][2] + b0, v3 = acc[mt][nt][3] + b1;
            if (RES) {
                float2 q0 = *(const float2*)(Cin + (size_t)row0 * N + col);
                float2 q1 = *(const float2*)(Cin + (size_t)(row0 + 8) * N + col);
                v0 += q0.x; v1 += q0.y; v2 += q1.x; v3 += q1.y;
            }
            if (RELU) {
                v0 = fmaxf(v0, 0.f); v1 = fmaxf(v1, 0.f);
                v2 = fmaxf(v2, 0.f); v3 = fmaxf(v3, 0.f);
            }
            if (OP == 2 && col < HID) {
                v0 *= 0.125f; v1 *= 0.125f; v2 *= 0.125f; v3 *= 0.125f;
            }
            if (OP >= 1) {
                v0 = roundtf(v0); v1 = roundtf(v1);
                v2 = roundtf(v2); v3 = roundtf(v3);
            }
            *(float2*)(C + (size_t)row0 * N + col) = make_float2(v0, v1);
            *(float2*)(C + (size_t)(row0 + 8) * N + col) = make_float2(v2, v3);
        }
    }
}

// ============== tensor-core flash attention (BQ=128, BK=64, dbl-buffered KV) ==============
// 256 threads = 8 warps x 16 q-rows. qkv pre-rounded tf32, Q pre-scaled 0.125.
// smem floats: Q[128][68] | K[2][64][68] | V[2][64][72] | P[128][68] | mask[2][64]
#define AQS 68
#define AVS 72
#define AOQ 0
#define AOK0 8704
#define AKSZ 4352
#define AOV0 17408
#define AVSZ 4608
#define AOP  26624
#define AOM0 35328
#define ATTN_SMEM ((35328 + 128) * 4)

__global__ void __launch_bounds__(256) attn_mma(const float* __restrict__ qkv,
                                                const int* __restrict__ src,
                                                float* __restrict__ O) {
    extern __shared__ float sa[];
    uint32_t* smu = (uint32_t*)sa;
    int bh = blockIdx.y;
    int b = bh >> 3, h = bh & 7;
    int q0 = blockIdx.x * 128;
    int tid = threadIdx.x;
    int lane = tid & 31, w = tid >> 5;
    int g = lane >> 2, tig = lane & 3;

    // load Q via cp.async (already tf32 + scaled): 128 rows
    const float* Qg = qkv + (size_t)(b * SEQ + q0) * QKV_STR + h * HDD;
#pragma unroll
    for (int i = tid; i < 2048; i += 256) {
        int row = i >> 4, c4 = (i & 15) << 2;
        cp16(smem_u32(smu + AOQ + row * AQS + c4), Qg + (size_t)row * QKV_STR + c4);
    }
    CP_COMMIT();

    auto load_kv = [&](int s, int kt) {
        const float* Kg = qkv + (size_t)(b * SEQ + kt * 64) * QKV_STR + HID + h * HDD;
        const float* Vg = Kg + HID;
#pragma unroll
        for (int i = tid; i < 1024; i += 256) {
            int row = i >> 4, c4 = (i & 15) << 2;
            cp16(smem_u32(smu + AOK0 + s * AKSZ + row * AQS + c4), Kg + (size_t)row * QKV_STR + c4);
            cp16(smem_u32(smu + AOV0 + s * AVSZ + row * AVS + c4), Vg + (size_t)row * QKV_STR + c4);
        }
        CP_COMMIT();
        if (tid < 64)
            sa[AOM0 + s * 64 + tid] = (src[b * SEQ + kt * 64 + tid] != 0) ? 0.f : -1e10f;
    };

    load_kv(0, 0);

    float o_acc[8][4];
#pragma unroll
    for (int nt = 0; nt < 8; nt++)
#pragma unroll
        for (int r = 0; r < 4; r++) o_acc[nt][r] = 0.f;
    float mr0 = -1e30f, mr1 = -1e30f, lr0 = 0.f, lr1 = 0.f;

    for (int kt = 0; kt < SEQ / 64; kt++) {
        int s = kt & 1;
        CP_WAIT(0);
        __syncthreads();                 // Q + KV(s) + mask(s) visible; stage s^1 free
        if (kt + 1 < SEQ / 64) load_kv(s ^ 1, kt + 1);
        const uint32_t* Ks = smu + AOK0 + s * AKSZ;
        const uint32_t* Vs = smu + AOV0 + s * AVSZ;
        const float* msk = sa + AOM0 + s * 64;

        // stage 1: S = Q @ K^T
        float sc[8][4];
#pragma unroll
        for (int nt = 0; nt < 8; nt++)
#pragma unroll
            for (int r = 0; r < 4; r++) sc[nt][r] = 0.f;
#pragma unroll
        for (int kk = 0; kk < 8; kk++) {
            uint32_t a[4];
            int r0 = (w * 16 + g) * AQS + kk * 8 + tig;
            int r1 = (w * 16 + 8 + g) * AQS + kk * 8 + tig;
            a[0] = smu[AOQ + r0]; a[1] = smu[AOQ + r1];
            a[2] = smu[AOQ + r0 + 4]; a[3] = smu[AOQ + r1 + 4];
#pragma unroll
            for (int nt = 0; nt < 8; nt++) {
                uint32_t bb[2];
                int rb = (nt * 8 + g) * AQS + kk * 8 + tig;
                bb[0] = Ks[rb]; bb[1] = Ks[rb + 4];
                mma_tf32(sc[nt], a, bb);
            }
        }

        // online softmax
        float m0 = -1e30f, m1 = -1e30f;
#pragma unroll
        for (int nt = 0; nt < 8; nt++) {
            float k0 = msk[nt * 8 + tig * 2];
            float k1 = msk[nt * 8 + tig * 2 + 1];
            sc[nt][0] += k0; sc[nt][1] += k1;
            sc[nt][2] += k0; sc[nt][3] += k1;
            m0 = fmaxf(m0, fmaxf(sc[nt][0], sc[nt][1]));
            m1 = fmaxf(m1, fmaxf(sc[nt][2], sc[nt][3]));
        }
        m0 = fmaxf(m0, __shfl_xor_sync(0xffffffffu, m0, 1));
        m0 = fmaxf(m0, __shfl_xor_sync(0xffffffffu, m0, 2));
        m1 = fmaxf(m1, __shfl_xor_sync(0xffffffffu, m1, 1));
        m1 = fmaxf(m1, __shfl_xor_sync(0xffffffffu, m1, 2));
        float mn0 = fmaxf(mr0, m0), mn1 = fmaxf(mr1, m1);
        float s0 = __expf(mr0 - mn0), s1 = __expf(mr1 - mn1);
        mr0 = mn0; mr1 = mn1;
        float l0 = 0.f, l1 = 0.f;
        int pr0 = AOP + (w * 16 + g) * AQS + tig * 2;
        int pr1 = AOP + (w * 16 + 8 + g) * AQS + tig * 2;
#pragma unroll
        for (int nt = 0; nt < 8; nt++) {
            float p0 = __expf(sc[nt][0] - mn0);
            float p1 = __expf(sc[nt][1] - mn0);
            float p2 = __expf(sc[nt][2] - mn1);
            float p3 = __expf(sc[nt][3] - mn1);
            l0 += p0 + p1; l1 += p2 + p3;
            smu[pr0 + nt * 8] = f2tf(p0); smu[pr0 + nt * 8 + 1] = f2tf(p1);
            smu[pr1 + nt * 8] = f2tf(p2); smu[pr1 + nt * 8 + 1] = f2tf(p3);
        }
        l0 += __shfl_xor_sync(0xffffffffu, l0, 1);
        l0 += __shfl_xor_sync(0xffffffffu, l0, 2);
        l1 += __shfl_xor_sync(0xffffffffu, l1, 1);
        l1 += __shfl_xor_sync(0xffffffffu, l1, 2);
        lr0 = lr0 * s0 + l0;
        lr1 = lr1 * s1 + l1;
#pragma unroll
        for (int nt = 0; nt < 8; nt++) {
            o_acc[nt][0] *= s0; o_acc[nt][1] *= s0;
            o_acc[nt][2] *= s1; o_acc[nt][3] *= s1;
        }
        __syncwarp();   // P rows are per-warp exclusive

        // stage 2: O += P @ V
#pragma unroll
        for (int kk = 0; kk < 8; kk++) {
            uint32_t a[4];
            int r0 = (w * 16 + g) * AQS + kk * 8 + tig;
            int r1 = (w * 16 + 8 + g) * AQS + kk * 8 + tig;
            a[0] = smu[AOP + r0]; a[1] = smu[AOP + r1];
            a[2] = smu[AOP + r0 + 4]; a[3] = smu[AOP + r1 + 4];
#pragma unroll
            for (int nt = 0; nt < 8; nt++) {
                uint32_t bb[2];
                bb[0] = Vs[(kk * 8 + tig) * AVS + nt * 8 + g];
                bb[1] = Vs[(kk * 8 + tig + 4) * AVS + nt * 8 + g];
                mma_tf32(o_acc[nt], a, bb);
            }
        }
    }

    float i0 = 1.f / lr0, i1 = 1.f / lr1;
    int row0 = b * SEQ + q0 + w * 16 + g;
    float* Ob = O + (size_t)row0 * HID + h * HDD;
#pragma unroll
    for (int nt = 0; nt < 8; nt++) {
        *(float2*)(Ob + nt * 8 + tig * 2) =
            make_float2(roundtf(o_acc[nt][0] * i0), roundtf(o_acc[nt][1] * i0));
        *(float2*)(Ob + 8 * HID + nt * 8 + tig * 2) =
            make_float2(roundtf(o_acc[nt][2] * i1), roundtf(o_acc[nt][3] * i1));
    }
}

// ---------------- fused weight transposes (tf32-rounded) ----------------
#define NJOBS 14
struct TParams {
    const float* in[NJOBS];
    float* out[NJOBS];
    int R[NJOBS], C[NJOBS], tstart[NJOBS];
};
__global__ void transpose_all(TParams p) {
    __shared__ float t[32][33];
    int tile = blockIdx.x;
    int j = 0;
#pragma unroll
    for (int q = 1; q < NJOBS; q++)
        if (tile >= p.tstart[q]) j = q;
    int local = tile - p.tstart[j];
    int R = p.R[j], Cc = p.C[j];
    int tilesX = Cc >> 5;
    int c0 = (local % tilesX) * 32, r0 = (local / tilesX) * 32;
    const float* in = p.in[j];
    float* out = p.out[j];
    int x = threadIdx.x, y = threadIdx.y;
#pragma unroll
    for (int i = 0; i < 32; i += 8) t[y + i][x] = in[(size_t)(r0 + y + i) * Cc + c0 + x];
    __syncthreads();
#pragma unroll
    for (int i = 0; i < 32; i += 8)
        out[(size_t)(c0 + y + i) * R + r0 + x] = roundtf(t[x][y + i]);
}

// ---------------- bias concat (both layers, one launch) ----------------
__global__ void concat_bias(const float* __restrict__ bq, const float* __restrict__ bk,
                            const float* __restrict__ bv, float* __restrict__ out) {
    int i = blockIdx.x * 256 + threadIdx.x;   // 0..3071
    int l = i / QKV_STR, r = i % QKV_STR;
    float v;
    if (r < HID) v = bq[l * HID + r];
    else if (r < 2 * HID) v = bk[l * HID + r - HID];
    else v = bv[l * HID + r - 2 * HID];
    out[i] = v;
}

// ---------------- embed + PE + time (MUFU fast math) ----------------
__global__ void embed_kernel(const int* __restrict__ src,
                             const float* __restrict__ tint,
                             const float* __restrict__ emb,
                             const float* __restrict__ timeW,
                             const float* __restrict__ timeb,
                             float* __restrict__ x) {
    int n = blockIdx.x;
    int d = threadIdx.x;
    int s = n & (SEQ - 1);
    int v = src[n];
    float e = emb[(size_t)v * DIM + d];
    int i2 = (d >> 1) * 2;
    float div = __expf((float)i2 * (-9.210340371976184f / (float)DIM));
    float ang = (float)s * div;
    float sn, cs;
    __sincosf(ang, &sn, &cs);
    float pe = (d & 1) ? cs : sn;
    float tv = tint[n];
    x[n * DIM + d] = e + pe + tv * timeW[d] + timeb[d];
}

// ---------------- neighbor mean aggregation (tf32-rounded out) ----------------
__global__ void agg_kernel(const int* __restrict__ nidx,
                           const int* __restrict__ ncnt,
                           const float* __restrict__ x,
                           float* __restrict__ agg) {
    int n = blockIdx.x;
    int d = threadIdx.x;
    int cnt = ncnt[n];
    float sum = 0.f;
    for (int j = 0; j < cnt; j++) {
        int idx = nidx[n * NMAXN + j];
        sum += x[idx * DIM + d];
    }
    int dv = cnt > 1 ? cnt : 1;
    agg[n * DIM + d] = roundtf(sum / (float)dv);
}

// ---------------- soc LN (warp-per-row, 8 rows/block) ----------------
__global__ void __launch_bounds__(256) soc_ln_kernel(const float* __restrict__ tmp,
                              const float* __restrict__ g,
                              const float* __restrict__ beta,
                              const int* __restrict__ ncnt,
                              const int* __restrict__ src,
                              float* __restrict__ x,
                              float* __restrict__ out_x) {
    int w = threadIdx.x >> 5, lane = threadIdx.x & 31;
    int n = blockIdx.x * 8 + w;
    const float4* r = (const float4*)(tmp + (size_t)n * DIM);
    float4 v[2];
    float s = 0.f;
#pragma unroll
    for (int j = 0; j < 2; j++) {
        v[j] = r[lane + 32 * j];
        s += v[j].x + v[j].y + v[j].z + v[j].w;
    }
    float mu = warpSum(s) * (1.f / DIM);
    float q = 0.f;
#pragma unroll
    for (int j = 0; j < 2; j++) {
        float a = v[j].x - mu, b2 = v[j].y - mu, c = v[j].z - mu, d2 = v[j].w - mu;
        q += a * a + b2 * b2 + c * c + d2 * d2;
    }
    float inv = rsqrtf(warpSum(q) * (1.f / DIM) + 1e-5f);
    int cnt = ncnt[n];
    int pad = (src[n] == 0);
    const float4* gg = (const float4*)g;
    const float4* bb = (const float4*)beta;
    const float4* xr = (const float4*)(x + (size_t)n * DIM);
    float4* xw = (float4*)(x + (size_t)n * DIM);
    float4* ow = (float4*)(out_x + (size_t)n * DIM);
#pragma unroll
    for (int j = 0; j < 2; j++) {
        float4 gv = gg[lane + 32 * j], bv = bb[lane + 32 * j];
        float4 xv = xr[lane + 32 * j];
        float y0 = fmaxf((v[j].x - mu) * inv * gv.x + bv.x, 0.f);
        float y1 = fmaxf((v[j].y - mu) * inv * gv.y + bv.y, 0.f);
        float y2 = fmaxf((v[j].z - mu) * inv * gv.z + bv.z, 0.f);
        float y3 = fmaxf((v[j].w - mu) * inv * gv.w + bv.w, 0.f);
        float s0 = (cnt > 0) ? y0 : xv.x; if (pad) s0 = 0.f;
        float s1 = (cnt > 0) ? y1 : xv.y; if (pad) s1 = 0.f;
        float s2 = (cnt > 0) ? y2 : xv.z; if (pad) s2 = 0.f;
        float s3 = (cnt > 0) ? y3 : xv.w; if (pad) s3 = 0.f;
        float o0 = xv.x + 0.2f * s0, o1 = xv.y + 0.2f * s1;
        float o2 = xv.z + 0.2f * s2, o3 = xv.w + 0.2f * s3;
        ow[lane + 32 * j] = make_float4(o0, o1, o2, o3);
        xw[lane + 32 * j] = make_float4(roundtf(o0), roundtf(o1), roundtf(o2), roundtf(o3));
    }
}

// ---------------- LayerNorm 512 (warp-per-row, 8 rows/block) ----------------
__global__ void __launch_bounds__(256) ln512_kernel(const float* __restrict__ in,
                             const float* __restrict__ g,
                             const float* __restrict__ b,
                             float* __restrict__ out, int round_out) {
    int w = threadIdx.x >> 5, lane = threadIdx.x & 31;
    int n = blockIdx.x * 8 + w;
    const float4* r = (const float4*)(in + (size_t)n * HID);
    float4 v[4];
    float s = 0.f;
#pragma unroll
    for (int j = 0; j < 4; j++) {
        v[j] = r[lane + 32 * j];
        s += v[j].x + v[j].y + v[j].z + v[j].w;
    }
    float mu = warpSum(s) * (1.f / HID);
    float q = 0.f;
#pragma unroll
    for (int j = 0; j < 4; j++) {
        float a = v[j].x - mu, b2 = v[j].y - mu, c = v[j].z - mu, d2 = v[j].w - mu;
        q += a * a + b2 * b2 + c * c + d2 * d2;
    }
    float inv = rsqrtf(warpSum(q) * (1.f / HID) + 1e-5f);
    const float4* gg = (const float4*)g;
    const float4* bb = (const float4*)b;
    float4* ow = (float4*)(out + (size_t)n * HID);
#pragma unroll
    for (int j = 0; j < 4; j++) {
        float4 gv = gg[lane + 32 * j], bv = bb[lane + 32 * j];
        float o0 = (v[j].x - mu) * inv * gv.x + bv.x;
        float o1 = (v[j].y - mu) * inv * gv.y + bv.y;
        float o2 = (v[j].z - mu) * inv * gv.z + bv.z;
        float o3 = (v[j].w - mu) * inv * gv.w + bv.w;
        if (round_out) {
            o0 = roundtf(o0); o1 = roundtf(o1); o2 = roundtf(o2); o3 = roundtf(o3);
        }
        ow[lane + 32 * j] = make_float4(o0, o1, o2, o3);
    }
}

// ---------------- host side ----------------
template <bool RELU, bool RES, int OP>
static void launch_gemm(const float* A, const float* Bt, const float* bias,
                        const float* Cin, float* C, int M, int Nn, int K) {
    dim3 grid(Nn / 128, M / 128);
    tc_gemm<RELU, RES, OP><<<grid, 128, GEMM_SMEM>>>(A, Bt, bias, Cin, C, M, Nn, K);
}

extern "C" void kernel_launch(void* const* d_in, const int* in_sizes, int n_in,
                              void* d_out, int out_size) {
    const int*   src   = (const int*)d_in[0];
    const int*   nidx  = (const int*)d_in[2];
    const int*   ncnt  = (const int*)d_in[3];
    const float* tint  = (const float*)d_in[4];
    const float* emb   = (const float*)d_in[5];
    const float* timeW = (const float*)d_in[6];
    const float* timeb = (const float*)d_in[7];
    const float* socW  = (const float*)d_in[8];
    const float* socb  = (const float*)d_in[9];
    const float* socg  = (const float*)d_in[10];
    const float* socbe = (const float*)d_in[11];
    const float* projW = (const float*)d_in[12];
    const float* projb = (const float*)d_in[13];
    const float* Wq    = (const float*)d_in[14];
    const float* bq    = (const float*)d_in[15];
    const float* Wk    = (const float*)d_in[16];
    const float* bk    = (const float*)d_in[17];
    const float* Wv    = (const float*)d_in[18];
    const float* bv    = (const float*)d_in[19];
    const float* Wo    = (const float*)d_in[20];
    const float* bo    = (const float*)d_in[21];
    const float* ln1g  = (const float*)d_in[22];
    const float* ln1b  = (const float*)d_in[23];
    const float* W1    = (const float*)d_in[24];
    const float* b1    = (const float*)d_in[25];
    const float* W2    = (const float*)d_in[26];
    const float* b2    = (const float*)d_in[27];
    const float* ln2g  = (const float*)d_in[28];
    const float* ln2b  = (const float*)d_in[29];

    float *x, *agg, *tmp, *h, *qkv, *o, *t1, *f1, *wt, *bqkv;
    void* p;
    cudaGetSymbolAddress(&p, g_x);    x    = (float*)p;
    cudaGetSymbolAddress(&p, g_agg);  agg  = (float*)p;
    cudaGetSymbolAddress(&p, g_tmp);  tmp  = (float*)p;
    cudaGetSymbolAddress(&p, g_h);    h    = (float*)p;
    cudaGetSymbolAddress(&p, g_qkv);  qkv  = (float*)p;
    cudaGetSymbolAddress(&p, g_o);    o    = (float*)p;
    cudaGetSymbolAddress(&p, g_t1);   t1   = (float*)p;
    cudaGetSymbolAddress(&p, g_f1);   f1   = (float*)p;
    cudaGetSymbolAddress(&p, g_wt);   wt   = (float*)p;
    cudaGetSymbolAddress(&p, g_bqkv); bqkv = (float*)p;

    cudaFuncSetAttribute(tc_gemm<false, true, 0>,  cudaFuncAttributeMaxDynamicSharedMemorySize, GEMM_SMEM);
    cudaFuncSetAttribute(tc_gemm<false, false, 1>, cudaFuncAttributeMaxDynamicSharedMemorySize, GEMM_SMEM);
    cudaFuncSetAttribute(tc_gemm<false, false, 2>, cudaFuncAttributeMaxDynamicSharedMemorySize, GEMM_SMEM);
    cudaFuncSetAttribute(tc_gemm<true, false, 1>,  cudaFuncAttributeMaxDynamicSharedMemorySize, GEMM_SMEM);
    cudaFuncSetAttribute(attn_mma, cudaFuncAttributeMaxDynamicSharedMemorySize, ATTN_SMEM);

    float* out_h = (float*)d_out;
    float* out_x = (float*)d_out + N_TOK * HID;

    // --- fused weight transposes (single launch, tf32-rounded) ---
    float* socT  = wt + WT_SOC;
    float* projT = wt + WT_PROJ;
    {
        TParams tp;
        int idx = 0, cum = 0;
        auto add = [&](const float* in, float* out, int R, int C) {
            tp.in[idx] = in; tp.out[idx] = out; tp.R[idx] = R; tp.C[idx] = C;
            tp.tstart[idx] = cum;
            cum += (R / 32) * (C / 32);
            idx++;
        };
        add(socW, socT, DIM, DIM);
        add(projW, projT, DIM, HID);
        for (int l = 0; l < 2; l++) {
            float* base = wt + WT_LAYER + (size_t)l * WT_PER_L;
            add(Wq + (size_t)l * HID * HID, base + L_QKV + 0 * 262144, HID, HID);
            add(Wk + (size_t)l * HID * HID, base + L_QKV + 1 * 262144, HID, HID);
            add(Wv + (size_t)l * HID * HID, base + L_QKV + 2 * 262144, HID, HID);
            add(Wo + (size_t)l * HID * HID, base + L_WO, HID, HID);
            add(W1 + (size_t)l * HID * PFF, base + L_W1, HID, PFF);
            add(W2 + (size_t)l * PFF * HID, base + L_W2, PFF, HID);
        }
        transpose_all<<<cum, dim3(32, 8)>>>(tp);
    }
    concat_bias<<<12, 256>>>(bq, bk, bv, bqkv);

    // front end
    embed_kernel<<<N_TOK, 256>>>(src, tint, emb, timeW, timeb, x);
    agg_kernel<<<N_TOK, 256>>>(nidx, ncnt, x, agg);
    launch_gemm<false, true, 0>(agg, socT, socb, x, tmp, N_TOK, DIM, DIM);
    soc_ln_kernel<<<N_TOK / 8, 256>>>(tmp, socg, socbe, ncnt, src, x, out_x);
    launch_gemm<false, false, 1>(x, projT, projb, (const float*)0, h, N_TOK, HID, DIM);

    for (int l = 0; l < 2; l++) {
        float* base = wt + WT_LAYER + (size_t)l * WT_PER_L;
        launch_gemm<false, false, 2>(h, base + L_QKV, bqkv + l * QKV_STR, (const float*)0,
                                     qkv, N_TOK, QKV_STR, HID);
        attn_mma<<<dim3(SEQ / 128, BATCH * NHD), 256, ATTN_SMEM>>>(qkv, src, o);
        launch_gemm<false, true, 0>(o, base + L_WO, bo + l * HID, h, t1, N_TOK, HID, HID);
        ln512_kernel<<<N_TOK / 8, 256>>>(t1, ln1g + l * HID, ln1b + l * HID, h, 1);
        launch_gemm<true, false, 1>(h, base + L_W1, b1 + l * PFF, (const float*)0, f1, N_TOK, PFF, HID);
        launch_gemm<false, true, 0>(f1, base + L_W2, b2 + l * HID, h, t1, N_TOK, HID, PFF);
        ln512_kernel<<<N_TOK / 8, 256>>>(t1, ln2g + l * HID, ln2b + l * HID,
                                         (l == 1) ? out_h : h, (l == 1) ? 0 : 1);
    }
}

// round 8
// speedup vs baseline: 6.8771x; 1.6542x over previous
#include <cuda_runtime.h>
#include <cuda_fp16.h>
#include <math.h>
#include <stdint.h>

// Problem dims (fixed)
#define BATCH 32
#define SEQ   512
#define N_TOK (BATCH * SEQ)   // 16384
#define DIM   256
#define HID   512
#define PFF   2048
#define NHD   8
#define HDD   64
#define NMAXN 15
#define QKV_STR 1536

// ---------------- scratch (device globals: allocation-free) ----------------
__device__ float  g_x[N_TOK * DIM];        // embed output (fp32)
__device__ float  g_tmp[N_TOK * DIM];      // soc gemm out
__device__ float  g_h32[N_TOK * HID];      // h fp32 (residual spine)
__device__ float  g_t1[N_TOK * HID];
__device__ float  g_bqkv[2 * QKV_STR];
__device__ __half g_x16[N_TOK * DIM];
__device__ __half g_agg16[N_TOK * DIM];
__device__ __half g_h16[N_TOK * HID];
__device__ __half g_qkv16[N_TOK * QKV_STR];
__device__ __half g_o16[N_TOK * HID];
__device__ __half g_ff16[N_TOK * PFF];
// transposed fp16 weights (same element counts as before, halves now)
#define WT_SOC   0
#define WT_PROJ  65536
#define WT_LAYER 196608
#define WT_PER_L 3145728
#define L_QKV 0
#define L_WO  786432
#define L_W1  1048576
#define L_W2  2097152
__device__ __half g_wt16[WT_LAYER + 2 * WT_PER_L];

// ======================= helpers =======================
__device__ __forceinline__ uint32_t smem_u32(const void* p) {
    uint32_t a;
    asm("{ .reg .u64 t; cvta.to.shared.u64 t, %1; cvt.u32.u64 %0, t; }" : "=r"(a) : "l"(p));
    return a;
}
__device__ __forceinline__ void cp16(uint32_t dst, const void* src) {
    asm volatile("cp.async.cg.shared.global [%0], [%1], 16;" :: "r"(dst), "l"(src));
}
#define CP_COMMIT() asm volatile("cp.async.commit_group;" ::: "memory")
#define CP_WAIT(n)  asm volatile("cp.async.wait_group %0;" :: "n"(n) : "memory")

__device__ __forceinline__ void mma_f16(float* c, const uint32_t* a, const uint32_t* b) {
    asm volatile(
        "mma.sync.aligned.m16n8k16.row.col.f32.f16.f16.f32 "
        "{%0,%1,%2,%3}, {%4,%5,%6,%7}, {%8,%9}, {%0,%1,%2,%3};\n"
        : "+f"(c[0]), "+f"(c[1]), "+f"(c[2]), "+f"(c[3])
        : "r"(a[0]), "r"(a[1]), "r"(a[2]), "r"(a[3]), "r"(b[0]), "r"(b[1]));
}
__device__ __forceinline__ void ldsm_x2_t(uint32_t& r0, uint32_t& r1, uint32_t addr) {
    asm volatile("ldmatrix.sync.aligned.m8n8.x2.trans.shared.b16 {%0,%1}, [%2];"
                 : "=r"(r0), "=r"(r1) : "r"(addr));
}
__device__ __forceinline__ uint32_t pack2h(float a, float b) {
    __half2 h = __floats2half2_rn(a, b);
    return *(uint32_t*)&h;
}
__device__ __forceinline__ float warpSum(float v) {
#pragma unroll
    for (int o = 16; o; o >>= 1) v += __shfl_xor_sync(0xffffffffu, v, o);
    return v;
}

// ============== fp16 tensor-core GEMM ==============
// 128x128 CTA tile, BK=32, 128 threads (4 warps = 2x2), warp tile 64x64, m16n8k16.
// smem rows: 40 halves (32 data + 8 pad) = 80 B; word stride 20 -> banks 4g+tig (CF).
// OUT: 0 = fp32 only, 1 = fp16 only, 2 = both, 3 = fp16 + scale cols<HID by 0.125
#define GSTAGE_B 20480     // (128*80)*2 matrices
#define GEMM_SMEM (2 * GSTAGE_B)

template <bool RELU, bool RES, int OUT>
__global__ void __launch_bounds__(128) tc_gemm(const __half* __restrict__ A,
                                               const __half* __restrict__ Bt,
                                               const float* __restrict__ bias,
                                               const float* __restrict__ Cin,
                                               float* __restrict__ C32,
                                               __half* __restrict__ C16,
                                               int M, int N, int K) {
    extern __shared__ char smc[];
    int tid = threadIdx.x;
    int m0 = blockIdx.y * 128, n0 = blockIdx.x * 128;
    int lane = tid & 31, wid = tid >> 5;
    int wm = wid & 1, wn = wid >> 1;
    int g = lane >> 2, tig = lane & 3;
    uint32_t sb = smem_u32(smc);

    float acc[4][8][4];
#pragma unroll
    for (int mt = 0; mt < 4; mt++)
#pragma unroll
        for (int nt = 0; nt < 8; nt++)
#pragma unroll
            for (int r = 0; r < 4; r++) acc[mt][nt][r] = 0.f;

    int nk = K >> 5;

    auto issue = [&](int s, int i) {
#pragma unroll
        for (int p = 0; p < 4; p++) {
            int idx = p * 128 + tid;
            int row = idx >> 2, c = idx & 3;
            uint32_t da = sb + (uint32_t)(s * GSTAGE_B + row * 80 + c * 16);
            uint32_t db = da + 10240;
            cp16(da, A + (size_t)(m0 + row) * K + i * 32 + c * 8);
            cp16(db, Bt + (size_t)(n0 + row) * K + i * 32 + c * 8);
        }
        CP_COMMIT();
    };

    issue(0, 0);
    for (int i = 0; i < nk; i++) {
        int s = i & 1;
        CP_WAIT(0);
        __syncthreads();
        if (i + 1 < nk) issue(s ^ 1, i + 1);
        const uint32_t* As = (const uint32_t*)(smc + s * GSTAGE_B);
        const uint32_t* Bs = As + 2560;
#pragma unroll
        for (int ks = 0; ks < 2; ks++) {
            uint32_t af[4][4], bf[8][2];
#pragma unroll
            for (int mt = 0; mt < 4; mt++) {
                int m = wm * 64 + mt * 16 + g;
                af[mt][0] = As[m * 20 + ks * 8 + tig];
                af[mt][1] = As[(m + 8) * 20 + ks * 8 + tig];
                af[mt][2] = As[m * 20 + ks * 8 + tig + 4];
                af[mt][3] = As[(m + 8) * 20 + ks * 8 + tig + 4];
            }
#pragma unroll
            for (int nt = 0; nt < 8; nt++) {
                int n = wn * 64 + nt * 8 + g;
                bf[nt][0] = Bs[n * 20 + ks * 8 + tig];
                bf[nt][1] = Bs[n * 20 + ks * 8 + tig + 4];
            }
#pragma unroll
            for (int mt = 0; mt < 4; mt++)
#pragma unroll
                for (int nt = 0; nt < 8; nt++)
                    mma_f16(acc[mt][nt], af[mt], bf[nt]);
        }
    }

#pragma unroll
    for (int mt = 0; mt < 4; mt++) {
#pragma unroll
        for (int nt = 0; nt < 8; nt++) {
            int row0 = m0 + wm * 64 + mt * 16 + g;
            int col = n0 + wn * 64 + nt * 8 + tig * 2;
            float b0 = __ldg(&bias[col]), b1 = __ldg(&bias[col + 1]);
            float v0 = acc[mt][nt][0] + b0, v1 = acc[mt][nt][1] + b1;
            float v2 = acc[mt][nt][2] + b0, v3 = acc[mt][nt][3] + b1;
            if (RES) {
                float2 q0 = *(const float2*)(Cin + (size_t)row0 * N + col);
                float2 q1 = *(const float2*)(Cin + (size_t)(row0 + 8) * N + col);
                v0 += q0.x; v1 += q0.y; v2 += q1.x; v3 += q1.y;
            }
            if (RELU) {
                v0 = fmaxf(v0, 0.f); v1 = fmaxf(v1, 0.f);
                v2 = fmaxf(v2, 0.f); v3 = fmaxf(v3, 0.f);
            }
            if (OUT == 3 && col < HID) {
                v0 *= 0.125f; v1 *= 0.125f; v2 *= 0.125f; v3 *= 0.125f;
            }
            if (OUT == 0 || OUT == 2) {
                *(float2*)(C32 + (size_t)row0 * N + col) = make_float2(v0, v1);
                *(float2*)(C32 + (size_t)(row0 + 8) * N + col) = make_float2(v2, v3);
            }
            if (OUT >= 1) {
                *(uint32_t*)(C16 + (size_t)row0 * N + col) = pack2h(v0, v1);
                *(uint32_t*)(C16 + (size_t)(row0 + 8) * N + col) = pack2h(v2, v3);
            }
        }
    }
}

// ============== fp16 tensor-core flash attention (BQ=128, BK=64, dbl-buf KV) ==============
// 256 threads = 8 warps x 16 q-rows. qkv16 packed [N,1536] halves, Q pre-scaled 0.125.
// half rows stride 72 (144 B). Layout (half offsets):
//   Q[128][72] @0 | K[2][64][72] @9216 | V[2][64][72] @18432 | P[128][72] @27648
//   masks (fp32): float offset 18432 (byte 73728)
#define HOQ  0
#define HOK0 9216
#define HKSZ 4608
#define HOV0 18432
#define HVSZ 4608
#define HOP  27648
#define FOM  18432
#define ATTN_SMEM (73728 + 512)

__global__ void __launch_bounds__(256) attn_mma(const __half* __restrict__ qkv,
                                                const int* __restrict__ src,
                                                __half* __restrict__ O) {
    extern __shared__ char sac[];
    float* saf = (float*)sac;
    const uint32_t* smw = (const uint32_t*)sac;   // half-pair (word) view
    uint32_t sb = smem_u32(sac);
    int bh = blockIdx.y;
    int b = bh >> 3, h = bh & 7;
    int q0 = blockIdx.x * 128;
    int tid = threadIdx.x;
    int lane = tid & 31, w = tid >> 5;
    int g = lane >> 2, tig = lane & 3;

    // Q load: 128 rows x 64 halves
    const __half* Qg = qkv + (size_t)(b * SEQ + q0) * QKV_STR + h * HDD;
#pragma unroll
    for (int p = 0; p < 4; p++) {
        int idx = p * 256 + tid;
        int row = idx >> 3, c = idx & 7;
        cp16(sb + (uint32_t)(row * 144 + c * 16), Qg + (size_t)row * QKV_STR + c * 8);
    }
    CP_COMMIT();

    auto load_kv = [&](int s, int kt) {
        const __half* Kg = qkv + (size_t)(b * SEQ + kt * 64) * QKV_STR + HID + h * HDD;
        const __half* Vg = Kg + HID;
#pragma unroll
        for (int p = 0; p < 2; p++) {
            int idx = p * 256 + tid;
            int row = idx >> 3, c = idx & 7;
            cp16(sb + (uint32_t)((HOK0 + s * HKSZ + row * 72) * 2 + c * 16),
                 Kg + (size_t)row * QKV_STR + c * 8);
            cp16(sb + (uint32_t)((HOV0 + s * HVSZ + row * 72) * 2 + c * 16),
                 Vg + (size_t)row * QKV_STR + c * 8);
        }
        CP_COMMIT();
        if (tid < 64)
            saf[FOM + s * 64 + tid] = (src[b * SEQ + kt * 64 + tid] != 0) ? 0.f : -1e10f;
    };

    load_kv(0, 0);

    float o_acc[8][4];
#pragma unroll
    for (int nt = 0; nt < 8; nt++)
#pragma unroll
        for (int r = 0; r < 4; r++) o_acc[nt][r] = 0.f;
    float mr0 = -1e30f, mr1 = -1e30f, lr0 = 0.f, lr1 = 0.f;

    for (int kt = 0; kt < SEQ / 64; kt++) {
        int s = kt & 1;
        CP_WAIT(0);
        __syncthreads();
        if (kt + 1 < SEQ / 64) load_kv(s ^ 1, kt + 1);
        int kbw = (HOK0 + s * HKSZ) >> 1;     // K base (words)
        uint32_t vbb = sb + (uint32_t)((HOV0 + s * HVSZ) * 2);  // V base (bytes)
        const float* msk = saf + FOM + s * 64;

        // stage 1: S = Q @ K^T  (A rows w*16..+15, k = hd 0..63)
        float sc[8][4];
#pragma unroll
        for (int nt = 0; nt < 8; nt++)
#pragma unroll
            for (int r = 0; r < 4; r++) sc[nt][r] = 0.f;
#pragma unroll
        for (int kk = 0; kk < 4; kk++) {
            uint32_t a[4];
            int r0 = (w * 16 + g) * 36 + kk * 8 + tig;
            int r1 = (w * 16 + 8 + g) * 36 + kk * 8 + tig;
            a[0] = smw[r0]; a[1] = smw[r1];
            a[2] = smw[r0 + 4]; a[3] = smw[r1 + 4];
#pragma unroll
            for (int nt = 0; nt < 8; nt++) {
                uint32_t bb[2];
                int rb = kbw + (nt * 8 + g) * 36 + kk * 8 + tig;
                bb[0] = smw[rb]; bb[1] = smw[rb + 4];
                mma_f16(sc[nt], a, bb);
            }
        }

        // online softmax (fp32)
        float m0 = -1e30f, m1 = -1e30f;
#pragma unroll
        for (int nt = 0; nt < 8; nt++) {
            float k0 = msk[nt * 8 + tig * 2];
            float k1 = msk[nt * 8 + tig * 2 + 1];
            sc[nt][0] += k0; sc[nt][1] += k1;
            sc[nt][2] += k0; sc[nt][3] += k1;
            m0 = fmaxf(m0, fmaxf(sc[nt][0], sc[nt][1]));
            m1 = fmaxf(m1, fmaxf(sc[nt][2], sc[nt][3]));
        }
        m0 = fmaxf(m0, __shfl_xor_sync(0xffffffffu, m0, 1));
        m0 = fmaxf(m0, __shfl_xor_sync(0xffffffffu, m0, 2));
        m1 = fmaxf(m1, __shfl_xor_sync(0xffffffffu, m1, 1));
        m1 = fmaxf(m1, __shfl_xor_sync(0xffffffffu, m1, 2));
        float mn0 = fmaxf(mr0, m0), mn1 = fmaxf(mr1, m1);
        float s0 = __expf(mr0 - mn0), s1 = __expf(mr1 - mn1);
        mr0 = mn0; mr1 = mn1;
        float l0 = 0.f, l1 = 0.f;
        uint32_t* smwp = (uint32_t*)sac;
        int pw0 = (HOP >> 1) + (w * 16 + g) * 36 + tig;
        int pw1 = (HOP >> 1) + (w * 16 + 8 + g) * 36 + tig;
#pragma unroll
        for (int nt = 0; nt < 8; nt++) {
            float p0 = __expf(sc[nt][0] - mn0);
            float p1 = __expf(sc[nt][1] - mn0);
            float p2 = __expf(sc[nt][2] - mn1);
            float p3 = __expf(sc[nt][3] - mn1);
            l0 += p0 + p1; l1 += p2 + p3;
            smwp[pw0 + nt * 4] = pack2h(p0, p1);
            smwp[pw1 + nt * 4] = pack2h(p2, p3);
        }
        l0 += __shfl_xor_sync(0xffffffffu, l0, 1);
        l0 += __shfl_xor_sync(0xffffffffu, l0, 2);
        l1 += __shfl_xor_sync(0xffffffffu, l1, 1);
        l1 += __shfl_xor_sync(0xffffffffu, l1, 2);
        lr0 = lr0 * s0 + l0;
        lr1 = lr1 * s1 + l1;
#pragma unroll
        for (int nt = 0; nt < 8; nt++) {
            o_acc[nt][0] *= s0; o_acc[nt][1] *= s0;
            o_acc[nt][2] *= s1; o_acc[nt][3] *= s1;
        }
        __syncwarp();   // P rows are per-warp exclusive

        // stage 2: O += P @ V  (B = V via ldmatrix.trans, no smem transpose)
        int j = lane & 15;
#pragma unroll
        for (int kk = 0; kk < 4; kk++) {
            uint32_t a[4];
            int r0 = (HOP >> 1) + (w * 16 + g) * 36 + kk * 8 + tig;
            int r1 = (HOP >> 1) + (w * 16 + 8 + g) * 36 + kk * 8 + tig;
            a[0] = smwp[r0]; a[1] = smwp[r1];
            a[2] = smwp[r0 + 4]; a[3] = smwp[r1 + 4];
            uint32_t vrow = vbb + (uint32_t)((kk * 16 + j) * 144);
#pragma unroll
            for (int nt = 0; nt < 8; nt++) {
                uint32_t bb0, bb1;
                ldsm_x2_t(bb0, bb1, vrow + nt * 16);
                uint32_t bb[2] = {bb0, bb1};
                mma_f16(o_acc[nt], a, bb);
            }
        }
    }

    float i0 = 1.f / lr0, i1 = 1.f / lr1;
    int row0 = b * SEQ + q0 + w * 16 + g;
    __half* Ob = O + (size_t)row0 * HID + h * HDD;
#pragma unroll
    for (int nt = 0; nt < 8; nt++) {
        *(uint32_t*)(Ob + nt * 8 + tig * 2) = pack2h(o_acc[nt][0] * i0, o_acc[nt][1] * i0);
        *(uint32_t*)(Ob + 8 * HID + nt * 8 + tig * 2) = pack2h(o_acc[nt][2] * i1, o_acc[nt][3] * i1);
    }
}

// ---------------- fused weight transposes (fp32 -> fp16 Bt[n][k]) ----------------
#define NJOBS 14
struct TParams {
    const float* in[NJOBS];
    __half* out[NJOBS];
    int R[NJOBS], C[NJOBS], tstart[NJOBS];
};
__global__ void transpose_all(TParams p) {
    __shared__ float t[32][33];
    int tile = blockIdx.x;
    int j = 0;
#pragma unroll
    for (int q = 1; q < NJOBS; q++)
        if (tile >= p.tstart[q]) j = q;
    int local = tile - p.tstart[j];
    int R = p.R[j], Cc = p.C[j];
    int tilesX = Cc >> 5;
    int c0 = (local % tilesX) * 32, r0 = (local / tilesX) * 32;
    const float* in = p.in[j];
    __half* out = p.out[j];
    int x = threadIdx.x, y = threadIdx.y;
#pragma unroll
    for (int i = 0; i < 32; i += 8) t[y + i][x] = in[(size_t)(r0 + y + i) * Cc + c0 + x];
    __syncthreads();
#pragma unroll
    for (int i = 0; i < 32; i += 8)
        out[(size_t)(c0 + y + i) * R + r0 + x] = __float2half_rn(t[x][y + i]);
}

// ---------------- bias concat (both layers, one launch) ----------------
__global__ void concat_bias(const float* __restrict__ bq, const float* __restrict__ bk,
                            const float* __restrict__ bv, float* __restrict__ out) {
    int i = blockIdx.x * 256 + threadIdx.x;
    int l = i / QKV_STR, r = i % QKV_STR;
    float v;
    if (r < HID) v = bq[l * HID + r];
    else if (r < 2 * HID) v = bk[l * HID + r - HID];
    else v = bv[l * HID + r - 2 * HID];
    out[i] = v;
}

// ---------------- embed + PE + time (MUFU fast math, fp32 out) ----------------
__global__ void embed_kernel(const int* __restrict__ src,
                             const float* __restrict__ tint,
                             const float* __restrict__ emb,
                             const float* __restrict__ timeW,
                             const float* __restrict__ timeb,
                             float* __restrict__ x) {
    int n = blockIdx.x;
    int d = threadIdx.x;
    int s = n & (SEQ - 1);
    int v = src[n];
    float e = emb[(size_t)v * DIM + d];
    int i2 = (d >> 1) * 2;
    float div = __expf((float)i2 * (-9.210340371976184f / (float)DIM));
    float ang = (float)s * div;
    float sn, cs;
    __sincosf(ang, &sn, &cs);
    float pe = (d & 1) ? cs : sn;
    float tv = tint[n];
    x[n * DIM + d] = e + pe + tv * timeW[d] + timeb[d];
}

// ---------------- neighbor mean aggregation (fp32 sums -> fp16 out) ----------------
__global__ void agg_kernel(const int* __restrict__ nidx,
                           const int* __restrict__ ncnt,
                           const float* __restrict__ x,
                           __half* __restrict__ agg) {
    int n = blockIdx.x;
    int d = threadIdx.x;
    int cnt = ncnt[n];
    float sum = 0.f;
    for (int j = 0; j < cnt; j++) {
        int idx = nidx[n * NMAXN + j];
        sum += x[idx * DIM + d];
    }
    int dv = cnt > 1 ? cnt : 1;
    agg[n * DIM + d] = __float2half_rn(sum / (float)dv);
}

// ---------------- soc LN (warp-per-row): writes out_x fp32 + x16 fp16 ----------------
__global__ void __launch_bounds__(256) soc_ln_kernel(const float* __restrict__ tmp,
                              const float* __restrict__ g,
                              const float* __restrict__ beta,
                              const int* __restrict__ ncnt,
                              const int* __restrict__ src,
                              const float* __restrict__ x,
                              __half* __restrict__ x16,
                              float* __restrict__ out_x) {
    int w = threadIdx.x >> 5, lane = threadIdx.x & 31;
    int n = blockIdx.x * 8 + w;
    const float4* r = (const float4*)(tmp + (size_t)n * DIM);
    float4 v[2];
    float s = 0.f;
#pragma unroll
    for (int j = 0; j < 2; j++) {
        v[j] = r[lane + 32 * j];
        s += v[j].x + v[j].y + v[j].z + v[j].w;
    }
    float mu = warpSum(s) * (1.f / DIM);
    float q = 0.f;
#pragma unroll
    for (int j = 0; j < 2; j++) {
        float a = v[j].x - mu, b2 = v[j].y - mu, c = v[j].z - mu, d2 = v[j].w - mu;
        q += a * a + b2 * b2 + c * c + d2 * d2;
    }
    float inv = rsqrtf(warpSum(q) * (1.f / DIM) + 1e-5f);
    int cnt = ncnt[n];
    int pad = (src[n] == 0);
    const float4* gg = (const float4*)g;
    const float4* bb = (const float4*)beta;
    const float4* xr = (const float4*)(x + (size_t)n * DIM);
    float4* ow = (float4*)(out_x + (size_t)n * DIM);
    uint32_t* xw = (uint32_t*)(x16 + (size_t)n * DIM);
#pragma unroll
    for (int j = 0; j < 2; j++) {
        float4 gv = gg[lane + 32 * j], bv = bb[lane + 32 * j];
        float4 xv = xr[lane + 32 * j];
        float y0 = fmaxf((v[j].x - mu) * inv * gv.x + bv.x, 0.f);
        float y1 = fmaxf((v[j].y - mu) * inv * gv.y + bv.y, 0.f);
        float y2 = fmaxf((v[j].z - mu) * inv * gv.z + bv.z, 0.f);
        float y3 = fmaxf((v[j].w - mu) * inv * gv.w + bv.w, 0.f);
        float s0 = (cnt > 0) ? y0 : xv.x; if (pad) s0 = 0.f;
        float s1 = (cnt > 0) ? y1 : xv.y; if (pad) s1 = 0.f;
        float s2 = (cnt > 0) ? y2 : xv.z; if (pad) s2 = 0.f;
        float s3 = (cnt > 0) ? y3 : xv.w; if (pad) s3 = 0.f;
        float o0 = xv.x + 0.2f * s0, o1 = xv.y + 0.2f * s1;
        float o2 = xv.z + 0.2f * s2, o3 = xv.w + 0.2f * s3;
        ow[lane + 32 * j] = make_float4(o0, o1, o2, o3);
        xw[(lane + 32 * j) * 2] = pack2h(o0, o1);
        xw[(lane + 32 * j) * 2 + 1] = pack2h(o2, o3);
    }
}

// ---------------- LayerNorm 512 (warp-per-row): out32 always, out16 optional ----------
__global__ void __launch_bounds__(256) ln512_kernel(const float* __restrict__ in,
                             const float* __restrict__ g,
                             const float* __restrict__ b,
                             float* __restrict__ out32,
                             __half* __restrict__ out16) {
    int w = threadIdx.x >> 5, lane = threadIdx.x & 31;
    int n = blockIdx.x * 8 + w;
    const float4* r = (const float4*)(in + (size_t)n * HID);
    float4 v[4];
    float s = 0.f;
#pragma unroll
    for (int j = 0; j < 4; j++) {
        v[j] = r[lane + 32 * j];
        s += v[j].x + v[j].y + v[j].z + v[j].w;
    }
    float mu = warpSum(s) * (1.f / HID);
    float q = 0.f;
#pragma unroll
    for (int j = 0; j < 4; j++) {
        float a = v[j].x - mu, b2 = v[j].y - mu, c = v[j].z - mu, d2 = v[j].w - mu;
        q += a * a + b2 * b2 + c * c + d2 * d2;
    }
    float inv = rsqrtf(warpSum(q) * (1.f / HID) + 1e-5f);
    const float4* gg = (const float4*)g;
    const float4* bb = (const float4*)b;
    float4* ow = (float4*)(out32 + (size_t)n * HID);
    uint32_t* hw = out16 ? (uint32_t*)(out16 + (size_t)n * HID) : (uint32_t*)0;
#pragma unroll
    for (int j = 0; j < 4; j++) {
        float4 gv = gg[lane + 32 * j], bv = bb[lane + 32 * j];
        float o0 = (v[j].x - mu) * inv * gv.x + bv.x;
        float o1 = (v[j].y - mu) * inv * gv.y + bv.y;
        float o2 = (v[j].z - mu) * inv * gv.z + bv.z;
        float o3 = (v[j].w - mu) * inv * gv.w + bv.w;
        ow[lane + 32 * j] = make_float4(o0, o1, o2, o3);
        if (hw) {
            hw[(lane + 32 * j) * 2] = pack2h(o0, o1);
            hw[(lane + 32 * j) * 2 + 1] = pack2h(o2, o3);
        }
    }
}

// ---------------- host side ----------------
template <bool RELU, bool RES, int OUT>
static void launch_gemm(const __half* A, const __half* Bt, const float* bias,
                        const float* Cin, float* C32, __half* C16, int M, int Nn, int K) {
    dim3 grid(Nn / 128, M / 128);
    tc_gemm<RELU, RES, OUT><<<grid, 128, GEMM_SMEM>>>(A, Bt, bias, Cin, C32, C16, M, Nn, K);
}

extern "C" void kernel_launch(void* const* d_in, const int* in_sizes, int n_in,
                              void* d_out, int out_size) {
    const int*   src   = (const int*)d_in[0];
    const int*   nidx  = (const int*)d_in[2];
    const int*   ncnt  = (const int*)d_in[3];
    const float* tint  = (const float*)d_in[4];
    const float* emb   = (const float*)d_in[5];
    const float* timeW = (const float*)d_in[6];
    const float* timeb = (const float*)d_in[7];
    const float* socW  = (const float*)d_in[8];
    const float* socb  = (const float*)d_in[9];
    const float* socg  = (const float*)d_in[10];
    const float* socbe = (const float*)d_in[11];
    const float* projW = (const float*)d_in[12];
    const float* projb = (const float*)d_in[13];
    const float* Wq    = (const float*)d_in[14];
    const float* bq    = (const float*)d_in[15];
    const float* Wk    = (const float*)d_in[16];
    const float* bk    = (const float*)d_in[17];
    const float* Wv    = (const float*)d_in[18];
    const float* bv    = (const float*)d_in[19];
    const float* Wo    = (const float*)d_in[20];
    const float* bo    = (const float*)d_in[21];
    const float* ln1g  = (const float*)d_in[22];
    const float* ln1b  = (const float*)d_in[23];
    const float* W1    = (const float*)d_in[24];
    const float* b1    = (const float*)d_in[25];
    const float* W2    = (const float*)d_in[26];
    const float* b2    = (const float*)d_in[27];
    const float* ln2g  = (const float*)d_in[28];
    const float* ln2b  = (const float*)d_in[29];

    float *x, *tmp, *h32, *t1, *bqkv;
    __half *x16, *agg16, *h16, *qkv16, *o16, *ff16, *wt16;
    void* p;
    cudaGetSymbolAddress(&p, g_x);     x     = (float*)p;
    cudaGetSymbolAddress(&p, g_tmp);   tmp   = (float*)p;
    cudaGetSymbolAddress(&p, g_h32);   h32   = (float*)p;
    cudaGetSymbolAddress(&p, g_t1);    t1    = (float*)p;
    cudaGetSymbolAddress(&p, g_bqkv);  bqkv  = (float*)p;
    cudaGetSymbolAddress(&p, g_x16);   x16   = (__half*)p;
    cudaGetSymbolAddress(&p, g_agg16); agg16 = (__half*)p;
    cudaGetSymbolAddress(&p, g_h16);   h16   = (__half*)p;
    cudaGetSymbolAddress(&p, g_qkv16); qkv16 = (__half*)p;
    cudaGetSymbolAddress(&p, g_o16);   o16   = (__half*)p;
    cudaGetSymbolAddress(&p, g_ff16);  ff16  = (__half*)p;
    cudaGetSymbolAddress(&p, g_wt16);  wt16  = (__half*)p;

    cudaFuncSetAttribute(tc_gemm<false, true, 0>,  cudaFuncAttributeMaxDynamicSharedMemorySize, GEMM_SMEM);
    cudaFuncSetAttribute(tc_gemm<false, false, 2>, cudaFuncAttributeMaxDynamicSharedMemorySize, GEMM_SMEM);
    cudaFuncSetAttribute(tc_gemm<false, false, 3>, cudaFuncAttributeMaxDynamicSharedMemorySize, GEMM_SMEM);
    cudaFuncSetAttribute(tc_gemm<true, false, 1>,  cudaFuncAttributeMaxDynamicSharedMemorySize, GEMM_SMEM);
    cudaFuncSetAttribute(attn_mma, cudaFuncAttributeMaxDynamicSharedMemorySize, ATTN_SMEM);

    float* out_h = (float*)d_out;
    float* out_x = (float*)d_out + N_TOK * HID;

    // --- fused weight transposes (single launch, fp32 -> fp16) ---
    __half* socT  = wt16 + WT_SOC;
    __half* projT = wt16 + WT_PROJ;
    {
        TParams tp;
        int idx = 0, cum = 0;
        auto add = [&](const float* in, __half* out, int R, int C) {
            tp.in[idx] = in; tp.out[idx] = out; tp.R[idx] = R; tp.C[idx] = C;
            tp.tstart[idx] = cum;
            cum += (R / 32) * (C / 32);
            idx++;
        };
        add(socW, socT, DIM, DIM);
        add(projW, projT, DIM, HID);
        for (int l = 0; l < 2; l++) {
            __half* base = wt16 + WT_LAYER + (size_t)l * WT_PER_L;
            add(Wq + (size_t)l * HID * HID, base + L_QKV + 0 * 262144, HID, HID);
            add(Wk + (size_t)l * HID * HID, base + L_QKV + 1 * 262144, HID, HID);
            add(Wv + (size_t)l * HID * HID, base + L_QKV + 2 * 262144, HID, HID);
            add(Wo + (size_t)l * HID * HID, base + L_WO, HID, HID);
            add(W1 + (size_t)l * HID * PFF, base + L_W1, HID, PFF);
            add(W2 + (size_t)l * PFF * HID, base + L_W2, PFF, HID);
        }
        transpose_all<<<cum, dim3(32, 8)>>>(tp);
    }
    concat_bias<<<12, 256>>>(bq, bk, bv, bqkv);

    // front end
    embed_kernel<<<N_TOK, 256>>>(src, tint, emb, timeW, timeb, x);
    agg_kernel<<<N_TOK, 256>>>(nidx, ncnt, x, agg16);
    // tmp = x + agg @ socW + socb (fp32 out)
    launch_gemm<false, true, 0>(agg16, socT, socb, x, tmp, (__half*)0, N_TOK, DIM, DIM);
    soc_ln_kernel<<<N_TOK / 8, 256>>>(tmp, socg, socbe, ncnt, src, x, x16, out_x);
    // h = x @ projW + projb (fp32 + fp16)
    launch_gemm<false, false, 2>(x16, projT, projb, (const float*)0, h32, h16, N_TOK, HID, DIM);

    for (int l = 0; l < 2; l++) {
        __half* base = wt16 + WT_LAYER + (size_t)l * WT_PER_L;
        // fused QKV -> fp16 (Q cols scaled by 1/8)
        launch_gemm<false, false, 3>(h16, base + L_QKV, bqkv + l * QKV_STR, (const float*)0,
                                     (float*)0, qkv16, N_TOK, QKV_STR, HID);
        attn_mma<<<dim3(SEQ / 128, BATCH * NHD), 256, ATTN_SMEM>>>(qkv16, src, o16);
        // t1 = h32 + o @ Wo + bo (fp32)
        launch_gemm<false, true, 0>(o16, base + L_WO, bo + l * HID, h32, t1, (__half*)0,
                                    N_TOK, HID, HID);
        ln512_kernel<<<N_TOK / 8, 256>>>(t1, ln1g + l * HID, ln1b + l * HID, h32, h16);
        // f = relu(h @ W1 + b1) -> fp16
        launch_gemm<true, false, 1>(h16, base + L_W1, b1 + l * PFF, (const float*)0,
                                    (float*)0, ff16, N_TOK, PFF, HID);
        // t1 = h32 + f @ W2 + b2 (fp32)
        launch_gemm<false, true, 0>(ff16, base + L_W2, b2 + l * HID, h32, t1, (__half*)0,
                                    N_TOK, HID, PFF);
        ln512_kernel<<<N_TOK / 8, 256>>>(t1, ln2g + l * HID, ln2b + l * HID,
                                         (l == 1) ? out_h : h32, (l == 1) ? (__half*)0 : h16);
    }
}